// round 12
// baseline (speedup 1.0000x reference)
#include <cuda_runtime.h>
#include <math.h>

#define CC   64
#define BB   16
#define HWD  160
#define PIX  (HWD*HWD)   // 25600
#define NE   4
#define NL   5
#define CICH 8

typedef unsigned long long u64;

// ---- scratch (static device globals; no allocation allowed) ----
__device__ __align__(16) float g_xs0[BB*CC*PIX];
__device__ __align__(16) float g_xs [BB*CC*PIX];
__device__ __align__(16) float g_k0 [BB*CC*PIX];
__device__ __align__(16) float g_a1 [BB*CC*41*41];
__device__ __align__(16) float g_a4 [BB*CC*121];
__device__ __align__(16) float g_part[BB*CC*100];
__device__ __align__(16) float g_expw[BB*NE];
__device__ int   g_seli[BB*2];
__device__ __align__(16) float g_wt [64*9*64];   // conv1 weights [ci][tap][co]

__device__ __forceinline__ float gelu_f(float v){
    return 0.5f*v*(1.0f+erff(v*0.70710678118654752440f));
}
__device__ __forceinline__ u64 pack2(float lo, float hi){
    u64 r; asm("mov.b64 %0, {%1, %2};" : "=l"(r) : "f"(lo), "f"(hi)); return r;
}
__device__ __forceinline__ void unpack2(u64 v, float& lo, float& hi){
    asm("mov.b64 {%0, %1}, %2;" : "=f"(lo), "=f"(hi) : "l"(v));
}
__device__ __forceinline__ u64 ffma2(u64 a, u64 b, u64 c){
    u64 d; asm("fma.rn.f32x2 %0, %1, %2, %3;" : "=l"(d) : "l"(a), "l"(b), "l"(c)); return d;
}

// ===== K0: one-time weight transpose for conv3 ==========================
__global__ void k_wtrans(const float* __restrict__ w){
    int idx = blockIdx.x*256 + threadIdx.x;   // idx over [ci][t][co]
    if(idx>=36864) return;
    int co = idx & 63;
    int t  = (idx>>6)%9;
    int ci = idx/576;
    g_wt[idx] = w[co*576 + ci*9 + t];
}

// ===== K1: FUSED conv3x3+gelu -> conv1x1(64->128)+shuffle ===============
// Tile rows padded to 72 floats (288B) so every duplicated-pair window
// read is a 16B-aligned LDS.128 fetching TWO packed operands at once.
// smem (floats): conv: tile2 [0,3456) wsm [3456,8064)
//                pw  : Xs    [0,8192) Wsm [8192,12288)
#define FUSED_SMEM_FLOATS 12288
__global__ __launch_bounds__(256) void k_conv3pw(const float* __restrict__ x,
        const float* __restrict__ bias,
        const float* __restrict__ pwgt, const float* __restrict__ pbias){
    extern __shared__ __align__(16) float sm[];
    float* tile2 = sm;            // [ci][6 rows][36 dup-pairs padded]
    float* wsm   = sm + 3456;     // [ci][tap][co]
    float* Xs    = sm;            // [64][128] after conv
    float* Wsm   = sm + 8192;     // [ci][co] pw weights per phase
    const int b   = blockIdx.z;
    const int gx0 = blockIdx.x*32;
    const int gy0 = blockIdx.y*4;
    const int tid = threadIdx.x;
    const int warp = tid>>5, lane = tid&31;
    const int r = lane>>3, xg = lane&7;
    const int co0 = warp*8;
    u64 acc2[4][4];
    #pragma unroll
    for(int jp=0;jp<4;jp++)
        #pragma unroll
        for(int p=0;p<4;p++) acc2[jp][p]=0ull;

    for(int c0=0;c0<64;c0+=CICH){
        __syncthreads();
        // input tile: 8 ci x 6x34 halo region, stored duplicated, stride 72
        for(int idx=tid; idx<CICH*204; idx+=256){
            int ci=idx/204, rem=idx-ci*204;
            int rr=rem/34, cc=rem-rr*34;
            int gy=gy0-1+rr, gx=gx0-1+cc;
            float v=0.f;
            if((unsigned)gy<160u && (unsigned)gx<160u)
                v = x[((b*64+c0+ci)*160+gy)*160+gx];
            *(float2*)&tile2[ci*432 + rr*72 + cc*2] = make_float2(v,v);
        }
        {
            const float4* wsrc = (const float4*)&g_wt[c0*576];
            float4* wdst = (float4*)wsm;
            #pragma unroll
            for(int rep=0; rep<5; rep++){
                int idx = tid + rep*256;
                if(idx<CICH*144) wdst[idx]=wsrc[idx];
            }
        }
        __syncthreads();
        #pragma unroll
        for(int ci=0; ci<CICH; ci++){
            const float* tb = &tile2[ci*432];
            u64 win2[3][6];
            #pragma unroll
            for(int ky=0;ky<3;ky++)
                #pragma unroll
                for(int c2=0;c2<6;c2+=2){
                    ulonglong2 f = *(const ulonglong2*)&tb[(r+ky)*72 + (xg*4+c2)*2];
                    win2[ky][c2]  =f.x;
                    win2[ky][c2+1]=f.y;
                }
            const float* wb = &wsm[ci*576];
            #pragma unroll
            for(int t=0;t<9;t++){
                const int ky=t/3, kx=t%3;
                ulonglong2 wa = *(const ulonglong2*)&wb[t*64+co0];
                ulonglong2 wc = *(const ulonglong2*)&wb[t*64+co0+4];
                u64 wp[4]={wa.x,wa.y,wc.x,wc.y};
                #pragma unroll
                for(int p=0;p<4;p++)
                    #pragma unroll
                    for(int jp=0;jp<4;jp++)
                        acc2[jp][p]=ffma2(win2[ky][p+kx], wp[jp], acc2[jp][p]);
            }
        }
    }
    __syncthreads();   // conv scratch dead; safe to overlay Xs

    #pragma unroll
    for(int jp=0;jp<4;jp++){
        int co=co0+2*jp;
        float bv0=bias[co], bv1=bias[co+1];
        float lo[4], hi[4];
        #pragma unroll
        for(int p=0;p<4;p++) unpack2(acc2[jp][p], lo[p], hi[p]);
        float4 o0, o1;
        o0.x=gelu_f(lo[0]+bv0); o0.y=gelu_f(lo[1]+bv0);
        o0.z=gelu_f(lo[2]+bv0); o0.w=gelu_f(lo[3]+bv0);
        o1.x=gelu_f(hi[0]+bv1); o1.y=gelu_f(hi[1]+bv1);
        o1.z=gelu_f(hi[2]+bv1); o1.w=gelu_f(hi[3]+bv1);
        *(float4*)&Xs[(co  )*128 + r*32 + xg*4]=o0;
        *(float4*)&Xs[(co+1)*128 + r*32 + xg*4]=o1;
    }

    const float4* Xs4=(const float4*)Xs;
    const int py = gy0 + (lane>>3);
    const int px = gx0 + (lane&7)*4;
    for(int phase=0; phase<2; phase++){
        __syncthreads();
        for(int i=tid;i<4096;i+=256){
            int ci=i>>6, co=i&63;
            Wsm[i]=pwgt[(phase*64+co)*64 + ci];
        }
        __syncthreads();
        u64 pacc[4][4];
        #pragma unroll
        for(int jp=0;jp<4;jp++)
            #pragma unroll
            for(int p=0;p<4;p++) pacc[jp][p]=0ull;
        for(int ci=0;ci<64;ci++){
            float4 xv = Xs4[ci*32+lane];
            ulonglong2 wa=*(const ulonglong2*)&Wsm[ci*64+co0];
            ulonglong2 wc=*(const ulonglong2*)&Wsm[ci*64+co0+4];
            u64 wp[4]={wa.x,wa.y,wc.x,wc.y};
            u64 xb[4];
            xb[0]=pack2(xv.x,xv.x); xb[1]=pack2(xv.y,xv.y);
            xb[2]=pack2(xv.z,xv.z); xb[3]=pack2(xv.w,xv.w);
            #pragma unroll
            for(int p=0;p<4;p++)
                #pragma unroll
                for(int jp=0;jp<4;jp++)
                    pacc[jp][p]=ffma2(xb[p], wp[jp], pacc[jp][p]);
        }
        #pragma unroll
        for(int jp=0;jp<4;jp++){
            int co = phase*64 + co0 + 2*jp;
            float lo[4], hi[4];
            #pragma unroll
            for(int p=0;p<4;p++) unpack2(pacc[jp][p], lo[p], hi[p]);
            #pragma unroll
            for(int half=0; half<2; half++){
                int c = co+half;
                float bv=pbias[c];
                float4 o;
                if(half==0){ o.x=lo[0]+bv;o.y=lo[1]+bv;o.z=lo[2]+bv;o.w=lo[3]+bv; }
                else       { o.x=hi[0]+bv;o.y=hi[1]+bv;o.z=hi[2]+bv;o.w=hi[3]+bv; }
                float* dst; int m;
                if(c<32)      { dst=g_xs0; m=2*c;        }
                else if(c<64) { dst=g_k0 ; m=2*(c-32);   }
                else if(c<96) { dst=g_xs0; m=2*(c-64)+1; }
                else          { dst=g_k0 ; m=2*(c-96)+1; }
                *(float4*)&dst[(b*64+m)*PIX + py*160 + px]=o;
            }
        }
    }
}

// ===== K3: depthwise separable 1x3 -> 3x1 + gelu (x4 vectorized) ========
__global__ __launch_bounds__(320) void k_sepdw(const float* __restrict__ w1,
        const float* __restrict__ b1, const float* __restrict__ w2,
        const float* __restrict__ b2){
    const int bc = blockIdx.z;
    const int c = bc & 63;
    const int tx = threadIdx.x;          // 0..39
    const int yy = blockIdx.y*8 + threadIdx.y;
    const int x4 = tx*4;
    const float* in = &g_xs0[bc*PIX];
    float a0=w1[c*3], a1=w1[c*3+1], a2=w1[c*3+2], ab=b1[c];
    float v0=w2[c*3], v1=w2[c*3+1], v2=w2[c*3+2], vb=b2[c];
    float t[3][4];
    #pragma unroll
    for(int ky=0;ky<3;ky++){
        int ry=yy-1+ky;
        if((unsigned)ry<160u){
            const float* row=&in[ry*160];
            float4 m = *(const float4*)&row[x4];
            float lv = (tx>0)?  row[x4-1] : 0.f;
            float rv = (tx<39)? row[x4+4] : 0.f;
            t[ky][0]=ab + a0*lv  + a1*m.x + a2*m.y;
            t[ky][1]=ab + a0*m.x + a1*m.y + a2*m.z;
            t[ky][2]=ab + a0*m.y + a1*m.z + a2*m.w;
            t[ky][3]=ab + a0*m.z + a1*m.w + a2*rv;
        } else {
            t[ky][0]=t[ky][1]=t[ky][2]=t[ky][3]=0.f;
        }
    }
    float4 o;
    o.x=gelu_f(vb + v0*t[0][0]+v1*t[1][0]+v2*t[2][0]);
    o.y=gelu_f(vb + v0*t[0][1]+v1*t[1][1]+v2*t[2][1]);
    o.z=gelu_f(vb + v0*t[0][2]+v1*t[1][2]+v2*t[2][2]);
    o.w=gelu_f(vb + v0*t[0][3]+v1*t[1][3]+v2*t[2][3]);
    *(float4*)&g_xs[bc*PIX + yy*160 + x4] = o;
    float s=o.x+o.y+o.z+o.w;
    #pragma unroll
    for(int off=16;off>0;off>>=1) s += __shfl_xor_sync(0xffffffffu, s, off);
    __shared__ float sred[10];
    int lt = threadIdx.y*40+tx;
    if((lt&31)==0) sred[lt>>5]=s;
    __syncthreads();
    if(lt==0){
        float tot=0.f;
        #pragma unroll
        for(int j=0;j<10;j++) tot+=sred[j];
        g_part[bc*20 + blockIdx.y] = tot;
    }
}

// ===== K4: reduce partials -> mean, softmax gate + top-2 (+indices) ======
__global__ void k_gate(const float* __restrict__ gw){
    const int b=blockIdx.x;
    const int tid=threadIdx.x;   // 64 threads
    __shared__ float mean[64];
    __shared__ float lg[NE];
    float s=0.f;
    const float* p=&g_part[(b*64+tid)*20];
    #pragma unroll
    for(int j=0;j<20;j++) s+=p[j];
    mean[tid]=s*(1.f/(float)PIX);
    __syncthreads();
    if(tid<NE){
        float acc=0.f;
        for(int cc=0;cc<64;cc++) acc+=mean[cc]*gw[tid*64+cc];
        lg[tid]=acc;
    }
    __syncthreads();
    if(tid==0){
        float mx=lg[0];
        for(int e=1;e<NE;e++) mx=fmaxf(mx,lg[e]);
        float sum=0.f, wv[NE];
        for(int e=0;e<NE;e++){ wv[e]=expf(lg[e]-mx); sum+=wv[e]; }
        for(int e=0;e<NE;e++) wv[e]/=sum;
        int i0=0;
        for(int e=1;e<NE;e++) if(wv[e]>wv[i0]) i0=e;
        int i1=-1;
        for(int e=0;e<NE;e++){ if(e==i0) continue; if(i1<0||wv[e]>wv[i1]) i1=e; }
        for(int e=0;e<NE;e++) g_expw[b*NE+e] = (e==i0||e==i1)? wv[e] : 0.f;
        g_seli[b*2  ]=i0;
        g_seli[b*2+1]=i1;
    }
}

// ===== K6a: depthwise 4x4 stride 4 pad 2 + gelu (160 -> 41) ==============
__global__ void k_agg1(const float* __restrict__ w, const float* __restrict__ bias){
    const int bc=blockIdx.z, c=bc&63;
    const int ox=blockIdx.x*16+threadIdx.x;
    const int oy=blockIdx.y*16+threadIdx.y;
    if(ox>=41||oy>=41) return;
    float acc=bias[c];
    const float* ip=&g_k0[bc*PIX];
    const float* wp=&w[c*16];
    #pragma unroll
    for(int ky=0;ky<4;ky++){
        int iy=oy*4-2+ky;
        if((unsigned)iy>=160u) continue;
        #pragma unroll
        for(int kx=0;kx<4;kx++){
            int ix=ox*4-2+kx;
            if((unsigned)ix<160u) acc+=wp[ky*4+kx]*ip[iy*160+ix];
        }
    }
    g_a1[bc*41*41+oy*41+ox]=gelu_f(acc);
}

// ===== K_CAL: fused agg2 (41->11) + caldw 3x3 + calpw 1x1, per batch ====
#define CAL_SMEM_FLOATS (7744+7744+4096)
__global__ __launch_bounds__(256) void k_cal(
        const float* __restrict__ aggw, const float* __restrict__ aggb,
        const float* __restrict__ cdw,  const float* __restrict__ cdb,
        const float* __restrict__ cpw,  const float* __restrict__ cpb){
    extern __shared__ __align__(16) float cs[];
    float* a2s = cs;
    float* a3s = cs + 7744;
    float* ws  = cs + 15488;
    const int b = blockIdx.x;
    const int tid = threadIdx.x;
    for(int idx=tid; idx<7744; idx+=256){
        int c=idx/121, t=idx-c*121, oy=t/11, ox=t-oy*11;
        const float* ip=&g_a1[(b*64+c)*1681];
        const float* wp=&aggw[c*16];
        float acc=aggb[c];
        #pragma unroll
        for(int ky=0;ky<4;ky++){
            int iy=oy*4-2+ky;
            if((unsigned)iy>=41u) continue;
            #pragma unroll
            for(int kx=0;kx<4;kx++){
                int ix=ox*4-2+kx;
                if((unsigned)ix<41u) acc+=wp[ky*4+kx]*ip[iy*41+ix];
            }
        }
        a2s[idx]=gelu_f(acc);
    }
    for(int i=tid;i<4096;i+=256) ws[i]=cpw[i];
    __syncthreads();
    for(int idx=tid; idx<7744; idx+=256){
        int c=idx/121, t=idx-c*121, y=t/11, xx=t-y*11;
        const float* ip=&a2s[c*121];
        const float* wp=&cdw[c*9];
        float acc=cdb[c];
        #pragma unroll
        for(int ky=0;ky<3;ky++){
            int iy=y-1+ky; if((unsigned)iy>=11u) continue;
            #pragma unroll
            for(int kx=0;kx<3;kx++){
                int ix=xx-1+kx;
                if((unsigned)ix<11u) acc+=wp[ky*3+kx]*ip[iy*11+ix];
            }
        }
        a3s[idx]=acc;
    }
    __syncthreads();
    const int p=tid&127, half=tid>>7;
    if(p<121){
        float iv[64];
        #pragma unroll 8
        for(int ci=0;ci<64;ci++) iv[ci]=a3s[ci*121+p];
        for(int j=0;j<32;j++){
            int co=half*32+j;
            float acc=cpb[co];
            #pragma unroll 8
            for(int ci=0;ci<64;ci++) acc+=ws[co*64+ci]*iv[ci];
            g_a4[(b*64+co)*121+p]=acc;
        }
    }
}

// ===== K_TAIL: top-2-sparse expert mix (+bilinear residual) + proj =======
// layout identical to R10 (49.5KB, 4 blocks/SM); weight loads upgraded
// to LDS.128 pairs.
#define TAIL_SMEM_FLOATS 12384
__global__ __launch_bounds__(256) void k_tail(
    const float* __restrict__ ew1,const float* __restrict__ eb1,
    const float* __restrict__ ew2,const float* __restrict__ eb2,
    const float* __restrict__ ew3,const float* __restrict__ eb3,
    const float* __restrict__ pjw,const float* __restrict__ pjb,
    float* __restrict__ out){
    extern __shared__ __align__(16) float sm[];
    float* Op   = sm;
    float* w1t  = sm;            // overlay: stage A only
    float* w2t  = sm + 768;
    float* Am   = sm + 8192;
    float* Bm   = sm + 9728;
    float* w3t  = sm + 11264;
    float* Wp   = sm + 8192;     // overlay: after stage B
    float* b1s  = sm + 12288;
    float* b2s  = sm + 12300;
    float* bias3f = sm + 12312;
    float* wes2 = sm + 12376;

    const int b = blockIdx.y;
    const int pixbase = blockIdx.x*128;
    const int tid=threadIdx.x;
    const int e0=g_seli[b*2], e1=g_seli[b*2+1];

    for(int idx=tid; idx<768; idx+=256){
        int ci=idx/12, i=idx-ci*12;
        int e = (i<6)? e0 : e1;
        int l = i%6;
        float v1=0.f, v2=0.f;
        if(l<5){
            v1=ew1[(e*5+l)*64+ci];
            v2=ew2[(e*5+l)*64+ci];
        }
        w1t[ci*12+i]=v1;
        w2t[ci*12+i]=v2;
    }
    for(int idx=tid; idx<768; idx+=256){
        int i=idx>>6, c=idx&63;
        int e = (i<6)? e0 : e1;
        int l = i%6;
        w3t[idx] = (l<5)? ew3[e*320 + c*5 + l] : 0.f;
    }
    if(tid<12){
        int e=(tid<6)?e0:e1; int l=tid%6;
        b1s[tid]=(l<5)? eb1[e*5+l] : 0.f;
        b2s[tid]=(l<5)? eb2[e*5+l] : 0.f;
    }
    if(tid<64){
        float acc=0.f;
        #pragma unroll
        for(int e=0;e<NE;e++) acc+=g_expw[b*4+e]*eb3[e*64+tid];
        bias3f[tid]=acc;
    }
    if(tid<2) wes2[tid]=g_expw[b*4 + ((tid==0)?e0:e1)];
    __syncthreads();

    const int p = tid&127, h = tid>>7;
    const int q = pixbase + p;

    // ---- stage A: selected-expert pre-activations --------------------
    {
        const float* wt   = h? w2t : w1t;
        const float* bsrc = h? b2s : b1s;
        u64 acc2[6];
        #pragma unroll
        for(int ip=0;ip<6;ip++) acc2[ip]=pack2(bsrc[2*ip], bsrc[2*ip+1]);

        int x0=0,x1=0,y0=0,y1=0;
        float c00=0,c01=0,c10=0,c11=0;
        if(h){
            int yy=q/160, xx=q-160*(q/160);
            const float scl=11.f/160.f;
            float tx=(xx+0.5f)*scl-0.5f, ty=(yy+0.5f)*scl-0.5f;
            int ix0=(int)floorf(tx), iy0=(int)floorf(ty);
            float fx=tx-(float)ix0, fy=ty-(float)iy0;
            x0=min(10,max(0,ix0)); x1=min(10,max(0,ix0+1));
            y0=min(10,max(0,iy0)); y1=min(10,max(0,iy0+1));
            c00=(1.f-fy)*(1.f-fx); c01=(1.f-fy)*fx;
            c10=fy*(1.f-fx);       c11=fy*fx;
        }
        const float* src = h? g_k0 : g_xs;
        const float* a4b = &g_a4[(size_t)b*64*121];
        for(int ci=0;ci<64;ci++){
            float col = src[(b*64+ci)*PIX + q];
            if(h){
                const float* a=&a4b[ci*121];
                col += c00*a[y0*11+x0]+c01*a[y0*11+x1]
                     + c10*a[y1*11+x0]+c11*a[y1*11+x1];
            }
            u64 cb = pack2(col,col);
            #pragma unroll
            for(int j=0;j<3;j++){
                ulonglong2 wv = *(const ulonglong2*)&wt[ci*12 + 4*j];
                acc2[2*j  ]=ffma2(cb, wv.x, acc2[2*j  ]);
                acc2[2*j+1]=ffma2(cb, wv.y, acc2[2*j+1]);
            }
        }
        float* dst = h? Bm : Am;
        #pragma unroll
        for(int ip=0;ip<6;ip++){
            float lo,hi; unpack2(acc2[ip],lo,hi);
            dst[(2*ip  )*128+p]=lo;
            dst[(2*ip+1)*128+p]=hi;
        }
    }
    __syncthreads();

    // ---- stage B: out_pre = xs + sum_sel we*(W3 (a*b)) + bias3f ------
    {
        const int c0=h*32;
        float pwv[12];
        #pragma unroll
        for(int i=0;i<12;i++)
            pwv[i]=wes2[i/6]*Am[i*128+p]*Bm[i*128+p];
        u64 acc[16];
        #pragma unroll
        for(int cp=0;cp<16;cp++){
            int c=c0+2*cp;
            float r0=g_xs[(b*64+c  )*PIX+q]+bias3f[c];
            float r1=g_xs[(b*64+c+1)*PIX+q]+bias3f[c+1];
            acc[cp]=pack2(r0,r1);
        }
        #pragma unroll
        for(int i=0;i<12;i++){
            u64 pb2=pack2(pwv[i],pwv[i]);
            #pragma unroll
            for(int cp=0;cp<16;cp+=2){
                ulonglong2 wv=*(const ulonglong2*)&w3t[i*64+c0+2*cp];
                acc[cp  ]=ffma2(pb2, wv.x, acc[cp  ]);
                acc[cp+1]=ffma2(pb2, wv.y, acc[cp+1]);
            }
        }
        #pragma unroll
        for(int cp=0;cp<16;cp++){
            float lo,hi; unpack2(acc[cp],lo,hi);
            Op[(c0+2*cp  )*128+p]=lo;
            Op[(c0+2*cp+1)*128+p]=hi;
        }
    }
    __syncthreads();

    for(int idx=tid; idx<4096; idx+=256){
        int ci=idx>>6, co=idx&63;
        Wp[idx]=pjw[co*64+ci];
    }
    __syncthreads();

    // ---- proj 1x1 64->64 : Op -> out -----------------------------------
    {
        const int warp=tid>>5, lane=tid&31;
        const int co0=warp*8;
        u64 pacc[4][4];
        #pragma unroll
        for(int jp=0;jp<4;jp++)
            #pragma unroll
            for(int pp=0;pp<4;pp++) pacc[jp][pp]=0ull;
        for(int ci=0;ci<64;ci++){
            float4 xv=*(const float4*)&Op[ci*128+lane*4];
            ulonglong2 wa=*(const ulonglong2*)&Wp[ci*64+co0];
            ulonglong2 wc=*(const ulonglong2*)&Wp[ci*64+co0+4];
            u64 wp2[4]={wa.x,wa.y,wc.x,wc.y};
            u64 xb[4];
            xb[0]=pack2(xv.x,xv.x); xb[1]=pack2(xv.y,xv.y);
            xb[2]=pack2(xv.z,xv.z); xb[3]=pack2(xv.w,xv.w);
            #pragma unroll
            for(int pp=0;pp<4;pp++)
                #pragma unroll
                for(int jp=0;jp<4;jp++)
                    pacc[jp][pp]=ffma2(xb[pp], wp2[jp], pacc[jp][pp]);
        }
        #pragma unroll
        for(int jp=0;jp<4;jp++){
            int co=co0+2*jp;
            float bv0=pjb[co], bv1=pjb[co+1];
            float lo[4],hi[4];
            #pragma unroll
            for(int pp=0;pp<4;pp++) unpack2(pacc[jp][pp],lo[pp],hi[pp]);
            float4 o0,o1;
            o0.x=lo[0]+bv0;o0.y=lo[1]+bv0;o0.z=lo[2]+bv0;o0.w=lo[3]+bv0;
            o1.x=hi[0]+bv1;o1.y=hi[1]+bv1;o1.z=hi[2]+bv1;o1.w=hi[3]+bv1;
            *(float4*)&out[(b*64+co  )*PIX+pixbase+lane*4]=o0;
            *(float4*)&out[(b*64+co+1)*PIX+pixbase+lane*4]=o1;
        }
    }
}

extern "C" void kernel_launch(void* const* d_in, const int* in_sizes, int n_in,
                              void* d_out, int out_size){
    (void)in_sizes; (void)n_in; (void)out_size;
    const float* x    =(const float*)d_in[0];
    const float* c1w1 =(const float*)d_in[1];
    const float* c1b1 =(const float*)d_in[2];
    const float* c1w2 =(const float*)d_in[3];
    const float* c1b2 =(const float*)d_in[4];
    const float* aggw =(const float*)d_in[5];
    const float* aggb =(const float*)d_in[6];
    const float* cdw  =(const float*)d_in[7];
    const float* cdb  =(const float*)d_in[8];
    const float* cpw  =(const float*)d_in[9];
    const float* cpb  =(const float*)d_in[10];
    const float* sw1  =(const float*)d_in[11];
    const float* sb1  =(const float*)d_in[12];
    const float* sw2  =(const float*)d_in[13];
    const float* sb2  =(const float*)d_in[14];
    const float* gw   =(const float*)d_in[15];
    const float* ew1  =(const float*)d_in[16];
    const float* eb1  =(const float*)d_in[17];
    const float* ew2  =(const float*)d_in[18];
    const float* eb2  =(const float*)d_in[19];
    const float* ew3  =(const float*)d_in[20];
    const float* eb3  =(const float*)d_in[21];
    const float* pw   =(const float*)d_in[22];
    const float* pb   =(const float*)d_in[23];
    float* out=(float*)d_out;

    cudaFuncSetAttribute(k_conv3pw, cudaFuncAttributeMaxDynamicSharedMemorySize,
                         FUSED_SMEM_FLOATS*4);
    cudaFuncSetAttribute(k_tail, cudaFuncAttributeMaxDynamicSharedMemorySize,
                         TAIL_SMEM_FLOATS*4);
    cudaFuncSetAttribute(k_cal, cudaFuncAttributeMaxDynamicSharedMemorySize,
                         CAL_SMEM_FLOATS*4);

    // side stream for the k-branch (fork/join pattern, capture-legal)
    cudaStream_t s2;
    cudaStreamCreateWithFlags(&s2, cudaStreamNonBlocking);
    cudaEvent_t e1, e2;
    cudaEventCreateWithFlags(&e1, cudaEventDisableTiming);
    cudaEventCreateWithFlags(&e2, cudaEventDisableTiming);

    k_wtrans    <<<144, 256>>>(c1w1);
    k_conv3pw   <<<dim3(5,40,16), 256, FUSED_SMEM_FLOATS*4>>>(x, c1b1, c1w2, c1b2);

    cudaEventRecord(e1, 0);
    cudaStreamWaitEvent(s2, e1, 0);

    // k-branch on side stream
    k_agg1      <<<dim3(3,3,BB*CC), dim3(16,16), 0, s2>>>(aggw, aggb);
    k_cal       <<<BB, 256, CAL_SMEM_FLOATS*4, s2>>>(aggw, aggb, cdw, cdb, cpw, cpb);

    // xs-branch on main stream (concurrent)
    k_sepdw     <<<dim3(1,20,BB*CC), dim3(40,8)>>>(sw1, sb1, sw2, sb2);
    k_gate      <<<BB, 64>>>(gw);

    cudaEventRecord(e2, s2);
    cudaStreamWaitEvent(0, e2, 0);

    k_tail      <<<dim3(200,16), 256, TAIL_SMEM_FLOATS*4>>>(
                    ew1, eb1, ew2, eb2, ew3, eb3, pw, pb, out);

    // destroy only when NOT capturing (during capture the objects must
    // outlive the capture; leaking them on the single capture call is fine)
    cudaStreamCaptureStatus st = cudaStreamCaptureStatusNone;
    if (cudaStreamIsCapturing(0, &st) == cudaSuccess &&
        st == cudaStreamCaptureStatusNone){
        cudaEventDestroy(e1);
        cudaEventDestroy(e2);
        cudaStreamDestroy(s2);
    }
}

// round 14
// speedup vs baseline: 1.0688x; 1.0688x over previous
#include <cuda_runtime.h>
#include <math.h>

#define CC   64
#define BB   16
#define HWD  160
#define PIX  (HWD*HWD)   // 25600
#define NE   4
#define NL   5
#define CICH 8

typedef unsigned long long u64;

// ---- scratch (static device globals; no allocation allowed) ----
__device__ __align__(16) float g_xs0[BB*CC*PIX];
__device__ __align__(16) float g_xs [BB*CC*PIX];
__device__ __align__(16) float g_k0 [BB*CC*PIX];
__device__ __align__(16) float g_a1 [BB*CC*41*41];
__device__ __align__(16) float g_a3 [BB*CC*121];
__device__ __align__(16) float g_a4 [BB*CC*121];
__device__ __align__(16) float g_part[BB*CC*100];
__device__ __align__(16) float g_expw[BB*NE];
__device__ int   g_seli[BB*2];
__device__ __align__(16) float g_wt [64*9*64];   // conv1 weights [ci][tap][co]

__device__ __forceinline__ float gelu_f(float v){
    return 0.5f*v*(1.0f+erff(v*0.70710678118654752440f));
}
__device__ __forceinline__ u64 pack2(float lo, float hi){
    u64 r; asm("mov.b64 %0, {%1, %2};" : "=l"(r) : "f"(lo), "f"(hi)); return r;
}
__device__ __forceinline__ void unpack2(u64 v, float& lo, float& hi){
    asm("mov.b64 {%0, %1}, %2;" : "=f"(lo), "=f"(hi) : "l"(v));
}
__device__ __forceinline__ u64 ffma2(u64 a, u64 b, u64 c){
    u64 d; asm("fma.rn.f32x2 %0, %1, %2, %3;" : "=l"(d) : "l"(a), "l"(b), "l"(c)); return d;
}

// ===== K0: one-time weight transpose for conv3 ==========================
__global__ void k_wtrans(const float* __restrict__ w){
    int idx = blockIdx.x*256 + threadIdx.x;   // idx over [ci][t][co]
    if(idx>=36864) return;
    int co = idx & 63;
    int t  = (idx>>6)%9;
    int ci = idx/576;
    g_wt[idx] = w[co*576 + ci*9 + t];
}

// ===== K1: FUSED conv3x3+gelu -> conv1x1(64->128)+shuffle (R11 body) ====
#define FUSED_SMEM_FLOATS 12288
__global__ __launch_bounds__(256) void k_conv3pw(const float* __restrict__ x,
        const float* __restrict__ bias,
        const float* __restrict__ pwgt, const float* __restrict__ pbias){
    extern __shared__ __align__(16) float sm[];
    float* tile2 = sm;            // [ci][6 rows][35 dup-pairs]
    float* wsm   = sm + 3360;     // [ci][tap][co]
    float* Xs    = sm;            // [64][128] after conv
    float* Wsm   = sm + 8192;     // [ci][co] pw weights per phase
    const int b   = blockIdx.z;
    const int gx0 = blockIdx.x*32;
    const int gy0 = blockIdx.y*4;
    const int tid = threadIdx.x;
    const int warp = tid>>5, lane = tid&31;
    const int r = lane>>3, xg = lane&7;
    const int co0 = warp*8;
    u64 acc2[4][4];
    #pragma unroll
    for(int jp=0;jp<4;jp++)
        #pragma unroll
        for(int p=0;p<4;p++) acc2[jp][p]=0ull;

    for(int c0=0;c0<64;c0+=CICH){
        __syncthreads();
        for(int idx=tid; idx<CICH*204; idx+=256){
            int ci=idx/204, rem=idx-ci*204;
            int rr=rem/34, cc=rem-rr*34;
            int gy=gy0-1+rr, gx=gx0-1+cc;
            float v=0.f;
            if((unsigned)gy<160u && (unsigned)gx<160u)
                v = x[((b*64+c0+ci)*160+gy)*160+gx];
            *(float2*)&tile2[ci*420 + rr*70 + cc*2] = make_float2(v,v);
        }
        {
            const float4* wsrc = (const float4*)&g_wt[c0*576];
            float4* wdst = (float4*)wsm;
            #pragma unroll
            for(int rep=0; rep<5; rep++){
                int idx = tid + rep*256;
                if(idx<CICH*144) wdst[idx]=wsrc[idx];
            }
        }
        __syncthreads();
        #pragma unroll
        for(int ci=0; ci<CICH; ci++){
            const float* tb = &tile2[ci*420];
            u64 win2[3][6];
            #pragma unroll
            for(int ky=0;ky<3;ky++)
                #pragma unroll
                for(int c2=0;c2<6;c2++)
                    win2[ky][c2] = *(const u64*)&tb[(r+ky)*70 + (xg*4+c2)*2];
            const float* wb = &wsm[ci*576];
            #pragma unroll
            for(int t=0;t<9;t++){
                const int ky=t/3, kx=t%3;
                u64 wp[4];
                #pragma unroll
                for(int jp=0;jp<4;jp++)
                    wp[jp]=*(const u64*)&wb[t*64+co0+2*jp];
                #pragma unroll
                for(int p=0;p<4;p++)
                    #pragma unroll
                    for(int jp=0;jp<4;jp++)
                        acc2[jp][p]=ffma2(win2[ky][p+kx], wp[jp], acc2[jp][p]);
            }
        }
    }
    __syncthreads();   // conv scratch dead; safe to overlay Xs

    #pragma unroll
    for(int jp=0;jp<4;jp++){
        int co=co0+2*jp;
        float bv0=bias[co], bv1=bias[co+1];
        float lo[4], hi[4];
        #pragma unroll
        for(int p=0;p<4;p++) unpack2(acc2[jp][p], lo[p], hi[p]);
        float4 o0, o1;
        o0.x=gelu_f(lo[0]+bv0); o0.y=gelu_f(lo[1]+bv0);
        o0.z=gelu_f(lo[2]+bv0); o0.w=gelu_f(lo[3]+bv0);
        o1.x=gelu_f(hi[0]+bv1); o1.y=gelu_f(hi[1]+bv1);
        o1.z=gelu_f(hi[2]+bv1); o1.w=gelu_f(hi[3]+bv1);
        *(float4*)&Xs[(co  )*128 + r*32 + xg*4]=o0;
        *(float4*)&Xs[(co+1)*128 + r*32 + xg*4]=o1;
    }

    const float4* Xs4=(const float4*)Xs;
    const int py = gy0 + (lane>>3);
    const int px = gx0 + (lane&7)*4;
    for(int phase=0; phase<2; phase++){
        __syncthreads();
        for(int i=tid;i<4096;i+=256){
            int ci=i>>6, co=i&63;
            Wsm[i]=pwgt[(phase*64+co)*64 + ci];
        }
        __syncthreads();
        u64 pacc[4][4];
        #pragma unroll
        for(int jp=0;jp<4;jp++)
            #pragma unroll
            for(int p=0;p<4;p++) pacc[jp][p]=0ull;
        for(int ci=0;ci<64;ci++){
            float4 xv = Xs4[ci*32+lane];
            u64 wp[4];
            #pragma unroll
            for(int jp=0;jp<4;jp++)
                wp[jp] = *(const u64*)&Wsm[ci*64 + co0 + 2*jp];
            u64 xb[4];
            xb[0]=pack2(xv.x,xv.x); xb[1]=pack2(xv.y,xv.y);
            xb[2]=pack2(xv.z,xv.z); xb[3]=pack2(xv.w,xv.w);
            #pragma unroll
            for(int p=0;p<4;p++)
                #pragma unroll
                for(int jp=0;jp<4;jp++)
                    pacc[jp][p]=ffma2(xb[p], wp[jp], pacc[jp][p]);
        }
        #pragma unroll
        for(int jp=0;jp<4;jp++){
            int co = phase*64 + co0 + 2*jp;
            float lo[4], hi[4];
            #pragma unroll
            for(int p=0;p<4;p++) unpack2(pacc[jp][p], lo[p], hi[p]);
            #pragma unroll
            for(int half=0; half<2; half++){
                int c = co+half;
                float bv=pbias[c];
                float4 o;
                if(half==0){ o.x=lo[0]+bv;o.y=lo[1]+bv;o.z=lo[2]+bv;o.w=lo[3]+bv; }
                else       { o.x=hi[0]+bv;o.y=hi[1]+bv;o.z=hi[2]+bv;o.w=hi[3]+bv; }
                float* dst; int m;
                if(c<32)      { dst=g_xs0; m=2*c;        }
                else if(c<64) { dst=g_k0 ; m=2*(c-32);   }
                else if(c<96) { dst=g_xs0; m=2*(c-64)+1; }
                else          { dst=g_k0 ; m=2*(c-96)+1; }
                *(float4*)&dst[(b*64+m)*PIX + py*160 + px]=o;
            }
        }
    }
}

// ===== K3: depthwise separable 1x3 -> 3x1 + gelu (x4 vectorized) ========
__global__ __launch_bounds__(320) void k_sepdw(const float* __restrict__ w1,
        const float* __restrict__ b1, const float* __restrict__ w2,
        const float* __restrict__ b2){
    const int bc = blockIdx.z;
    const int c = bc & 63;
    const int tx = threadIdx.x;          // 0..39
    const int yy = blockIdx.y*8 + threadIdx.y;
    const int x4 = tx*4;
    const float* in = &g_xs0[bc*PIX];
    float a0=w1[c*3], a1=w1[c*3+1], a2=w1[c*3+2], ab=b1[c];
    float v0=w2[c*3], v1=w2[c*3+1], v2=w2[c*3+2], vb=b2[c];
    float t[3][4];
    #pragma unroll
    for(int ky=0;ky<3;ky++){
        int ry=yy-1+ky;
        if((unsigned)ry<160u){
            const float* row=&in[ry*160];
            float4 m = *(const float4*)&row[x4];
            float lv = (tx>0)?  row[x4-1] : 0.f;
            float rv = (tx<39)? row[x4+4] : 0.f;
            t[ky][0]=ab + a0*lv  + a1*m.x + a2*m.y;
            t[ky][1]=ab + a0*m.x + a1*m.y + a2*m.z;
            t[ky][2]=ab + a0*m.y + a1*m.z + a2*m.w;
            t[ky][3]=ab + a0*m.z + a1*m.w + a2*rv;
        } else {
            t[ky][0]=t[ky][1]=t[ky][2]=t[ky][3]=0.f;
        }
    }
    float4 o;
    o.x=gelu_f(vb + v0*t[0][0]+v1*t[1][0]+v2*t[2][0]);
    o.y=gelu_f(vb + v0*t[0][1]+v1*t[1][1]+v2*t[2][1]);
    o.z=gelu_f(vb + v0*t[0][2]+v1*t[1][2]+v2*t[2][2]);
    o.w=gelu_f(vb + v0*t[0][3]+v1*t[1][3]+v2*t[2][3]);
    *(float4*)&g_xs[bc*PIX + yy*160 + x4] = o;
    float s=o.x+o.y+o.z+o.w;
    #pragma unroll
    for(int off=16;off>0;off>>=1) s += __shfl_xor_sync(0xffffffffu, s, off);
    __shared__ float sred[10];
    int lt = threadIdx.y*40+tx;
    if((lt&31)==0) sred[lt>>5]=s;
    __syncthreads();
    if(lt==0){
        float tot=0.f;
        #pragma unroll
        for(int j=0;j<10;j++) tot+=sred[j];
        g_part[bc*20 + blockIdx.y] = tot;
    }
}

// ===== K4: reduce partials -> mean, softmax gate + top-2 (+indices) ======
__global__ void k_gate(const float* __restrict__ gw){
    const int b=blockIdx.x;
    const int tid=threadIdx.x;   // 64 threads
    __shared__ float mean[64];
    __shared__ float lg[NE];
    float s=0.f;
    const float* p=&g_part[(b*64+tid)*20];
    #pragma unroll
    for(int j=0;j<20;j++) s+=p[j];
    mean[tid]=s*(1.f/(float)PIX);
    __syncthreads();
    if(tid<NE){
        float acc=0.f;
        for(int cc=0;cc<64;cc++) acc+=mean[cc]*gw[tid*64+cc];
        lg[tid]=acc;
    }
    __syncthreads();
    if(tid==0){
        float mx=lg[0];
        for(int e=1;e<NE;e++) mx=fmaxf(mx,lg[e]);
        float sum=0.f, wv[NE];
        for(int e=0;e<NE;e++){ wv[e]=expf(lg[e]-mx); sum+=wv[e]; }
        for(int e=0;e<NE;e++) wv[e]/=sum;
        int i0=0;
        for(int e=1;e<NE;e++) if(wv[e]>wv[i0]) i0=e;
        int i1=-1;
        for(int e=0;e<NE;e++){ if(e==i0) continue; if(i1<0||wv[e]>wv[i1]) i1=e; }
        for(int e=0;e<NE;e++) g_expw[b*NE+e] = (e==i0||e==i1)? wv[e] : 0.f;
        g_seli[b*2  ]=i0;
        g_seli[b*2+1]=i1;
    }
}

// ===== K6a: depthwise 4x4 stride 4 pad 2 + gelu (160 -> 41) ==============
__global__ void k_agg1(const float* __restrict__ w, const float* __restrict__ bias){
    const int bc=blockIdx.z, c=bc&63;
    const int ox=blockIdx.x*16+threadIdx.x;
    const int oy=blockIdx.y*16+threadIdx.y;
    if(ox>=41||oy>=41) return;
    float acc=bias[c];
    const float* ip=&g_k0[bc*PIX];
    const float* wp=&w[c*16];
    #pragma unroll
    for(int ky=0;ky<4;ky++){
        int iy=oy*4-2+ky;
        if((unsigned)iy>=160u) continue;
        #pragma unroll
        for(int kx=0;kx<4;kx++){
            int ix=ox*4-2+kx;
            if((unsigned)ix<160u) acc+=wp[ky*4+kx]*ip[iy*160+ix];
        }
    }
    g_a1[bc*41*41+oy*41+ox]=gelu_f(acc);
}

// ===== K6b: agg2 (41->11) + caldw 3x3, ONE (b,c) PER BLOCK (1024 blocks) =
__global__ __launch_bounds__(128) void k_agg2dw(
        const float* __restrict__ aggw, const float* __restrict__ aggb,
        const float* __restrict__ cdw,  const float* __restrict__ cdb){
    __shared__ float a2s[121];
    const int c = blockIdx.x, b = blockIdx.y;
    const int bc = b*64+c;
    const int t = threadIdx.x;
    if(t<121){
        int oy=t/11, ox=t-oy*11;
        const float* ip=&g_a1[bc*1681];
        const float* wp=&aggw[c*16];
        float acc=aggb[c];
        #pragma unroll
        for(int ky=0;ky<4;ky++){
            int iy=oy*4-2+ky;
            if((unsigned)iy>=41u) continue;
            #pragma unroll
            for(int kx=0;kx<4;kx++){
                int ix=ox*4-2+kx;
                if((unsigned)ix<41u) acc+=wp[ky*4+kx]*ip[iy*41+ix];
            }
        }
        a2s[t]=gelu_f(acc);
    }
    __syncthreads();
    if(t<121){
        int y=t/11, xx=t-y*11;
        const float* wp=&cdw[c*9];
        float acc=cdb[c];
        #pragma unroll
        for(int ky=0;ky<3;ky++){
            int iy=y-1+ky; if((unsigned)iy>=11u) continue;
            #pragma unroll
            for(int kx=0;kx<3;kx++){
                int ix=xx-1+kx;
                if((unsigned)ix<11u) acc+=wp[ky*3+kx]*a2s[iy*11+ix];
            }
        }
        g_a3[bc*121+t]=acc;
    }
}

// ===== K6c: pointwise 64->64 on the 11x11 maps ===========================
__global__ __launch_bounds__(256) void k_calpw(const float* __restrict__ cpw,
                                               const float* __restrict__ cpb){
    __shared__ float ws[4096];
    const int b=blockIdx.x;
    for(int i=threadIdx.x;i<4096;i+=256) ws[i]=cpw[i];
    __syncthreads();
    const int p=threadIdx.x&127, half=threadIdx.x>>7;
    if(p<121){
        float iv[64];
        #pragma unroll 8
        for(int ci=0;ci<64;ci++) iv[ci]=g_a3[(b*64+ci)*121+p];
        for(int j=0;j<32;j++){
            int co=half*32+j;
            float acc=cpb[co];
            #pragma unroll 8
            for(int ci=0;ci<64;ci++) acc+=ws[co*64+ci]*iv[ci];
            g_a4[(b*64+co)*121+p]=acc;
        }
    }
}

// ===== K_TAIL: top-2-sparse expert mix (+bilinear residual) + proj =======
// (R11 body: 49.5KB smem, u64 weight loads)
#define TAIL_SMEM_FLOATS 12384
__global__ __launch_bounds__(256) void k_tail(
    const float* __restrict__ ew1,const float* __restrict__ eb1,
    const float* __restrict__ ew2,const float* __restrict__ eb2,
    const float* __restrict__ ew3,const float* __restrict__ eb3,
    const float* __restrict__ pjw,const float* __restrict__ pjb,
    float* __restrict__ out){
    extern __shared__ __align__(16) float sm[];
    float* Op   = sm;
    float* w1t  = sm;            // overlay: stage A only
    float* w2t  = sm + 768;
    float* Am   = sm + 8192;
    float* Bm   = sm + 9728;
    float* w3t  = sm + 11264;
    float* Wp   = sm + 8192;     // overlay: after stage B
    float* b1s  = sm + 12288;
    float* b2s  = sm + 12300;
    float* bias3f = sm + 12312;
    float* wes2 = sm + 12376;

    const int b = blockIdx.y;
    const int pixbase = blockIdx.x*128;
    const int tid=threadIdx.x;
    const int e0=g_seli[b*2], e1=g_seli[b*2+1];

    for(int idx=tid; idx<768; idx+=256){
        int ci=idx/12, i=idx-ci*12;
        int e = (i<6)? e0 : e1;
        int l = i%6;
        float v1=0.f, v2=0.f;
        if(l<5){
            v1=ew1[(e*5+l)*64+ci];
            v2=ew2[(e*5+l)*64+ci];
        }
        w1t[ci*12+i]=v1;
        w2t[ci*12+i]=v2;
    }
    for(int idx=tid; idx<768; idx+=256){
        int i=idx>>6, c=idx&63;
        int e = (i<6)? e0 : e1;
        int l = i%6;
        w3t[idx] = (l<5)? ew3[e*320 + c*5 + l] : 0.f;
    }
    if(tid<12){
        int e=(tid<6)?e0:e1; int l=tid%6;
        b1s[tid]=(l<5)? eb1[e*5+l] : 0.f;
        b2s[tid]=(l<5)? eb2[e*5+l] : 0.f;
    }
    if(tid<64){
        float acc=0.f;
        #pragma unroll
        for(int e=0;e<NE;e++) acc+=g_expw[b*4+e]*eb3[e*64+tid];
        bias3f[tid]=acc;
    }
    if(tid<2) wes2[tid]=g_expw[b*4 + ((tid==0)?e0:e1)];
    __syncthreads();

    const int p = tid&127, h = tid>>7;
    const int q = pixbase + p;

    // ---- stage A: selected-expert pre-activations --------------------
    {
        const float* wt   = h? w2t : w1t;
        const float* bsrc = h? b2s : b1s;
        u64 acc2[6];
        #pragma unroll
        for(int ip=0;ip<6;ip++) acc2[ip]=pack2(bsrc[2*ip], bsrc[2*ip+1]);

        int x0=0,x1=0,y0=0,y1=0;
        float c00=0,c01=0,c10=0,c11=0;
        if(h){
            int yy=q/160, xx=q-160*(q/160);
            const float scl=11.f/160.f;
            float tx=(xx+0.5f)*scl-0.5f, ty=(yy+0.5f)*scl-0.5f;
            int ix0=(int)floorf(tx), iy0=(int)floorf(ty);
            float fx=tx-(float)ix0, fy=ty-(float)iy0;
            x0=min(10,max(0,ix0)); x1=min(10,max(0,ix0+1));
            y0=min(10,max(0,iy0)); y1=min(10,max(0,iy0+1));
            c00=(1.f-fy)*(1.f-fx); c01=(1.f-fy)*fx;
            c10=fy*(1.f-fx);       c11=fy*fx;
        }
        const float* src = h? g_k0 : g_xs;
        const float* a4b = &g_a4[(size_t)b*64*121];
        for(int ci=0;ci<64;ci++){
            float col = src[(b*64+ci)*PIX + q];
            if(h){
                const float* a=&a4b[ci*121];
                col += c00*a[y0*11+x0]+c01*a[y0*11+x1]
                     + c10*a[y1*11+x0]+c11*a[y1*11+x1];
            }
            u64 cb = pack2(col,col);
            #pragma unroll
            for(int ip=0;ip<6;ip++)
                acc2[ip]=ffma2(cb, *(const u64*)&wt[ci*12+2*ip], acc2[ip]);
        }
        float* dst = h? Bm : Am;
        #pragma unroll
        for(int ip=0;ip<6;ip++){
            float lo,hi; unpack2(acc2[ip],lo,hi);
            dst[(2*ip  )*128+p]=lo;
            dst[(2*ip+1)*128+p]=hi;
        }
    }
    __syncthreads();

    // ---- stage B: out_pre = xs + sum_sel we*(W3 (a*b)) + bias3f ------
    {
        const int c0=h*32;
        float pwv[12];
        #pragma unroll
        for(int i=0;i<12;i++)
            pwv[i]=wes2[i/6]*Am[i*128+p]*Bm[i*128+p];
        u64 acc[16];
        #pragma unroll
        for(int cp=0;cp<16;cp++){
            int c=c0+2*cp;
            float r0=g_xs[(b*64+c  )*PIX+q]+bias3f[c];
            float r1=g_xs[(b*64+c+1)*PIX+q]+bias3f[c+1];
            acc[cp]=pack2(r0,r1);
        }
        #pragma unroll
        for(int i=0;i<12;i++){
            u64 pb2=pack2(pwv[i],pwv[i]);
            #pragma unroll
            for(int cp=0;cp<16;cp++)
                acc[cp]=ffma2(pb2, *(const u64*)&w3t[i*64+c0+2*cp], acc[cp]);
        }
        #pragma unroll
        for(int cp=0;cp<16;cp++){
            float lo,hi; unpack2(acc[cp],lo,hi);
            Op[(c0+2*cp  )*128+p]=lo;
            Op[(c0+2*cp+1)*128+p]=hi;
        }
    }
    __syncthreads();

    for(int idx=tid; idx<4096; idx+=256){
        int ci=idx>>6, co=idx&63;
        Wp[idx]=pjw[co*64+ci];
    }
    __syncthreads();

    // ---- proj 1x1 64->64 : Op -> out -----------------------------------
    {
        const int warp=tid>>5, lane=tid&31;
        const int co0=warp*8;
        u64 pacc[4][4];
        #pragma unroll
        for(int jp=0;jp<4;jp++)
            #pragma unroll
            for(int pp=0;pp<4;pp++) pacc[jp][pp]=0ull;
        for(int ci=0;ci<64;ci++){
            float4 xv=*(const float4*)&Op[ci*128+lane*4];
            u64 wp2[4];
            #pragma unroll
            for(int jp=0;jp<4;jp++)
                wp2[jp]=*(const u64*)&Wp[ci*64+co0+2*jp];
            u64 xb[4];
            xb[0]=pack2(xv.x,xv.x); xb[1]=pack2(xv.y,xv.y);
            xb[2]=pack2(xv.z,xv.z); xb[3]=pack2(xv.w,xv.w);
            #pragma unroll
            for(int pp=0;pp<4;pp++)
                #pragma unroll
                for(int jp=0;jp<4;jp++)
                    pacc[jp][pp]=ffma2(xb[pp], wp2[jp], pacc[jp][pp]);
        }
        #pragma unroll
        for(int jp=0;jp<4;jp++){
            int co=co0+2*jp;
            float bv0=pjb[co], bv1=pjb[co+1];
            float lo[4],hi[4];
            #pragma unroll
            for(int pp=0;pp<4;pp++) unpack2(pacc[jp][pp],lo[pp],hi[pp]);
            float4 o0,o1;
            o0.x=lo[0]+bv0;o0.y=lo[1]+bv0;o0.z=lo[2]+bv0;o0.w=lo[3]+bv0;
            o1.x=hi[0]+bv1;o1.y=hi[1]+bv1;o1.z=hi[2]+bv1;o1.w=hi[3]+bv1;
            *(float4*)&out[(b*64+co  )*PIX+pixbase+lane*4]=o0;
            *(float4*)&out[(b*64+co+1)*PIX+pixbase+lane*4]=o1;
        }
    }
}

extern "C" void kernel_launch(void* const* d_in, const int* in_sizes, int n_in,
                              void* d_out, int out_size){
    (void)in_sizes; (void)n_in; (void)out_size;
    const float* x    =(const float*)d_in[0];
    const float* c1w1 =(const float*)d_in[1];
    const float* c1b1 =(const float*)d_in[2];
    const float* c1w2 =(const float*)d_in[3];
    const float* c1b2 =(const float*)d_in[4];
    const float* aggw =(const float*)d_in[5];
    const float* aggb =(const float*)d_in[6];
    const float* cdw  =(const float*)d_in[7];
    const float* cdb  =(const float*)d_in[8];
    const float* cpw  =(const float*)d_in[9];
    const float* cpb  =(const float*)d_in[10];
    const float* sw1  =(const float*)d_in[11];
    const float* sb1  =(const float*)d_in[12];
    const float* sw2  =(const float*)d_in[13];
    const float* sb2  =(const float*)d_in[14];
    const float* gw   =(const float*)d_in[15];
    const float* ew1  =(const float*)d_in[16];
    const float* eb1  =(const float*)d_in[17];
    const float* ew2  =(const float*)d_in[18];
    const float* eb2  =(const float*)d_in[19];
    const float* ew3  =(const float*)d_in[20];
    const float* eb3  =(const float*)d_in[21];
    const float* pw   =(const float*)d_in[22];
    const float* pb   =(const float*)d_in[23];
    float* out=(float*)d_out;

    cudaFuncSetAttribute(k_conv3pw, cudaFuncAttributeMaxDynamicSharedMemorySize,
                         FUSED_SMEM_FLOATS*4);
    cudaFuncSetAttribute(k_tail, cudaFuncAttributeMaxDynamicSharedMemorySize,
                         TAIL_SMEM_FLOATS*4);

    // side stream for the k-branch (fork/join pattern, capture-legal)
    cudaStream_t s2;
    cudaStreamCreateWithFlags(&s2, cudaStreamNonBlocking);
    cudaEvent_t e1, e2;
    cudaEventCreateWithFlags(&e1, cudaEventDisableTiming);
    cudaEventCreateWithFlags(&e2, cudaEventDisableTiming);

    k_wtrans    <<<144, 256>>>(c1w1);
    k_conv3pw   <<<dim3(5,40,16), 256, FUSED_SMEM_FLOATS*4>>>(x, c1b1, c1w2, c1b2);

    cudaEventRecord(e1, 0);
    cudaStreamWaitEvent(s2, e1, 0);

    // k-branch on side stream
    k_agg1      <<<dim3(3,3,BB*CC), dim3(16,16), 0, s2>>>(aggw, aggb);
    k_agg2dw    <<<dim3(CC,BB), 128, 0, s2>>>(aggw, aggb, cdw, cdb);
    k_calpw     <<<BB, 256, 0, s2>>>(cpw, cpb);

    // xs-branch on main stream (concurrent)
    k_sepdw     <<<dim3(1,20,BB*CC), dim3(40,8)>>>(sw1, sb1, sw2, sb2);
    k_gate      <<<BB, 64>>>(gw);

    cudaEventRecord(e2, s2);
    cudaStreamWaitEvent(0, e2, 0);

    k_tail      <<<dim3(200,16), 256, TAIL_SMEM_FLOATS*4>>>(
                    ew1, eb1, ew2, eb2, ew3, eb3, pw, pb, out);

    // destroy only when NOT capturing (during capture the objects must
    // outlive the capture; leaking them on the single capture call is fine)
    cudaStreamCaptureStatus st = cudaStreamCaptureStatusNone;
    if (cudaStreamIsCapturing(0, &st) == cudaSuccess &&
        st == cudaStreamCaptureStatusNone){
        cudaEventDestroy(e1);
        cudaEventDestroy(e2);
        cudaStreamDestroy(s2);
    }
}

// round 15
// speedup vs baseline: 1.0789x; 1.0095x over previous
#include <cuda_runtime.h>
#include <math.h>

#define CC   64
#define BB   16
#define HWD  160
#define PIX  (HWD*HWD)   // 25600
#define NE   4
#define NL   5
#define CICH 8

typedef unsigned long long u64;

// ---- scratch (static device globals; no allocation allowed) ----
__device__ __align__(16) float g_xs0[BB*CC*PIX];
__device__ __align__(16) float g_xs [BB*CC*PIX];
__device__ __align__(16) float g_k0 [BB*CC*PIX];
__device__ __align__(16) float g_a1 [BB*CC*41*41];
__device__ __align__(16) float g_a3 [BB*CC*121];
__device__ __align__(16) float g_a4 [BB*CC*121];
__device__ __align__(16) float g_part[BB*CC*100];
__device__ __align__(16) float g_expw[BB*NE];
__device__ int   g_seli[BB*2];
__device__ __align__(16) float g_wt [64*9*64];   // conv1 weights [ci][tap][co]

__device__ __forceinline__ float gelu_f(float v){
    return 0.5f*v*(1.0f+erff(v*0.70710678118654752440f));
}
__device__ __forceinline__ u64 pack2(float lo, float hi){
    u64 r; asm("mov.b64 %0, {%1, %2};" : "=l"(r) : "f"(lo), "f"(hi)); return r;
}
__device__ __forceinline__ void unpack2(u64 v, float& lo, float& hi){
    asm("mov.b64 {%0, %1}, %2;" : "=f"(lo), "=f"(hi) : "l"(v));
}
__device__ __forceinline__ u64 ffma2(u64 a, u64 b, u64 c){
    u64 d; asm("fma.rn.f32x2 %0, %1, %2, %3;" : "=l"(d) : "l"(a), "l"(b), "l"(c)); return d;
}

// ===== K0: one-time weight transpose for conv3 ==========================
__global__ void k_wtrans(const float* __restrict__ w){
    int idx = blockIdx.x*256 + threadIdx.x;   // idx over [ci][t][co]
    if(idx>=36864) return;
    int co = idx & 63;
    int t  = (idx>>6)%9;
    int ci = idx/576;
    g_wt[idx] = w[co*576 + ci*9 + t];
}

// ===== K1: FUSED conv3x3+gelu -> conv1x1(64->128)+shuffle ===============
// Window loads: per-lane u64 (LDS.128 here causes 32*(r+xg) mod 128 bank
// aliasing — measured regression in R12). Weight loads: warp-UNIFORM
// broadcast addresses -> LDS.128 is conflict-free and halves issue slots.
#define FUSED_SMEM_FLOATS 12288
__global__ __launch_bounds__(256) void k_conv3pw(const float* __restrict__ x,
        const float* __restrict__ bias,
        const float* __restrict__ pwgt, const float* __restrict__ pbias){
    extern __shared__ __align__(16) float sm[];
    float* tile2 = sm;            // [ci][6 rows][35 dup-pairs]
    float* wsm   = sm + 3360;     // [ci][tap][co]
    float* Xs    = sm;            // [64][128] after conv
    float* Wsm   = sm + 8192;     // [ci][co] pw weights per phase
    const int b   = blockIdx.z;
    const int gx0 = blockIdx.x*32;
    const int gy0 = blockIdx.y*4;
    const int tid = threadIdx.x;
    const int warp = tid>>5, lane = tid&31;
    const int r = lane>>3, xg = lane&7;
    const int co0 = warp*8;
    u64 acc2[4][4];
    #pragma unroll
    for(int jp=0;jp<4;jp++)
        #pragma unroll
        for(int p=0;p<4;p++) acc2[jp][p]=0ull;

    for(int c0=0;c0<64;c0+=CICH){
        __syncthreads();
        for(int idx=tid; idx<CICH*204; idx+=256){
            int ci=idx/204, rem=idx-ci*204;
            int rr=rem/34, cc=rem-rr*34;
            int gy=gy0-1+rr, gx=gx0-1+cc;
            float v=0.f;
            if((unsigned)gy<160u && (unsigned)gx<160u)
                v = x[((b*64+c0+ci)*160+gy)*160+gx];
            *(float2*)&tile2[ci*420 + rr*70 + cc*2] = make_float2(v,v);
        }
        {
            const float4* wsrc = (const float4*)&g_wt[c0*576];
            float4* wdst = (float4*)wsm;
            #pragma unroll
            for(int rep=0; rep<5; rep++){
                int idx = tid + rep*256;
                if(idx<CICH*144) wdst[idx]=wsrc[idx];
            }
        }
        __syncthreads();
        #pragma unroll
        for(int ci=0; ci<CICH; ci++){
            const float* tb = &tile2[ci*420];
            u64 win2[3][6];
            #pragma unroll
            for(int ky=0;ky<3;ky++)
                #pragma unroll
                for(int c2=0;c2<6;c2++)
                    win2[ky][c2] = *(const u64*)&tb[(r+ky)*70 + (xg*4+c2)*2];
            const float* wb = &wsm[ci*576];
            #pragma unroll
            for(int t=0;t<9;t++){
                const int ky=t/3, kx=t%3;
                // uniform broadcast -> LDS.128 safe
                ulonglong2 wa = *(const ulonglong2*)&wb[t*64+co0];
                ulonglong2 wc = *(const ulonglong2*)&wb[t*64+co0+4];
                u64 wp[4]={wa.x,wa.y,wc.x,wc.y};
                #pragma unroll
                for(int p=0;p<4;p++)
                    #pragma unroll
                    for(int jp=0;jp<4;jp++)
                        acc2[jp][p]=ffma2(win2[ky][p+kx], wp[jp], acc2[jp][p]);
            }
        }
    }
    __syncthreads();   // conv scratch dead; safe to overlay Xs

    #pragma unroll
    for(int jp=0;jp<4;jp++){
        int co=co0+2*jp;
        float bv0=bias[co], bv1=bias[co+1];
        float lo[4], hi[4];
        #pragma unroll
        for(int p=0;p<4;p++) unpack2(acc2[jp][p], lo[p], hi[p]);
        float4 o0, o1;
        o0.x=gelu_f(lo[0]+bv0); o0.y=gelu_f(lo[1]+bv0);
        o0.z=gelu_f(lo[2]+bv0); o0.w=gelu_f(lo[3]+bv0);
        o1.x=gelu_f(hi[0]+bv1); o1.y=gelu_f(hi[1]+bv1);
        o1.z=gelu_f(hi[2]+bv1); o1.w=gelu_f(hi[3]+bv1);
        *(float4*)&Xs[(co  )*128 + r*32 + xg*4]=o0;
        *(float4*)&Xs[(co+1)*128 + r*32 + xg*4]=o1;
    }

    const float4* Xs4=(const float4*)Xs;
    const int py = gy0 + (lane>>3);
    const int px = gx0 + (lane&7)*4;
    for(int phase=0; phase<2; phase++){
        __syncthreads();
        for(int i=tid;i<4096;i+=256){
            int ci=i>>6, co=i&63;
            Wsm[i]=pwgt[(phase*64+co)*64 + ci];
        }
        __syncthreads();
        u64 pacc[4][4];
        #pragma unroll
        for(int jp=0;jp<4;jp++)
            #pragma unroll
            for(int p=0;p<4;p++) pacc[jp][p]=0ull;
        for(int ci=0;ci<64;ci++){
            float4 xv = Xs4[ci*32+lane];
            ulonglong2 wa=*(const ulonglong2*)&Wsm[ci*64+co0];
            ulonglong2 wc=*(const ulonglong2*)&Wsm[ci*64+co0+4];
            u64 wp[4]={wa.x,wa.y,wc.x,wc.y};
            u64 xb[4];
            xb[0]=pack2(xv.x,xv.x); xb[1]=pack2(xv.y,xv.y);
            xb[2]=pack2(xv.z,xv.z); xb[3]=pack2(xv.w,xv.w);
            #pragma unroll
            for(int p=0;p<4;p++)
                #pragma unroll
                for(int jp=0;jp<4;jp++)
                    pacc[jp][p]=ffma2(xb[p], wp[jp], pacc[jp][p]);
        }
        #pragma unroll
        for(int jp=0;jp<4;jp++){
            int co = phase*64 + co0 + 2*jp;
            float lo[4], hi[4];
            #pragma unroll
            for(int p=0;p<4;p++) unpack2(pacc[jp][p], lo[p], hi[p]);
            #pragma unroll
            for(int half=0; half<2; half++){
                int c = co+half;
                float bv=pbias[c];
                float4 o;
                if(half==0){ o.x=lo[0]+bv;o.y=lo[1]+bv;o.z=lo[2]+bv;o.w=lo[3]+bv; }
                else       { o.x=hi[0]+bv;o.y=hi[1]+bv;o.z=hi[2]+bv;o.w=hi[3]+bv; }
                float* dst; int m;
                if(c<32)      { dst=g_xs0; m=2*c;        }
                else if(c<64) { dst=g_k0 ; m=2*(c-32);   }
                else if(c<96) { dst=g_xs0; m=2*(c-64)+1; }
                else          { dst=g_k0 ; m=2*(c-96)+1; }
                *(float4*)&dst[(b*64+m)*PIX + py*160 + px]=o;
            }
        }
    }
}

// ===== K3: depthwise separable 1x3 -> 3x1 + gelu (x4 vectorized) ========
__global__ __launch_bounds__(320) void k_sepdw(const float* __restrict__ w1,
        const float* __restrict__ b1, const float* __restrict__ w2,
        const float* __restrict__ b2){
    const int bc = blockIdx.z;
    const int c = bc & 63;
    const int tx = threadIdx.x;          // 0..39
    const int yy = blockIdx.y*8 + threadIdx.y;
    const int x4 = tx*4;
    const float* in = &g_xs0[bc*PIX];
    float a0=w1[c*3], a1=w1[c*3+1], a2=w1[c*3+2], ab=b1[c];
    float v0=w2[c*3], v1=w2[c*3+1], v2=w2[c*3+2], vb=b2[c];
    float t[3][4];
    #pragma unroll
    for(int ky=0;ky<3;ky++){
        int ry=yy-1+ky;
        if((unsigned)ry<160u){
            const float* row=&in[ry*160];
            float4 m = *(const float4*)&row[x4];
            float lv = (tx>0)?  row[x4-1] : 0.f;
            float rv = (tx<39)? row[x4+4] : 0.f;
            t[ky][0]=ab + a0*lv  + a1*m.x + a2*m.y;
            t[ky][1]=ab + a0*m.x + a1*m.y + a2*m.z;
            t[ky][2]=ab + a0*m.y + a1*m.z + a2*m.w;
            t[ky][3]=ab + a0*m.z + a1*m.w + a2*rv;
        } else {
            t[ky][0]=t[ky][1]=t[ky][2]=t[ky][3]=0.f;
        }
    }
    float4 o;
    o.x=gelu_f(vb + v0*t[0][0]+v1*t[1][0]+v2*t[2][0]);
    o.y=gelu_f(vb + v0*t[0][1]+v1*t[1][1]+v2*t[2][1]);
    o.z=gelu_f(vb + v0*t[0][2]+v1*t[1][2]+v2*t[2][2]);
    o.w=gelu_f(vb + v0*t[0][3]+v1*t[1][3]+v2*t[2][3]);
    *(float4*)&g_xs[bc*PIX + yy*160 + x4] = o;
    float s=o.x+o.y+o.z+o.w;
    #pragma unroll
    for(int off=16;off>0;off>>=1) s += __shfl_xor_sync(0xffffffffu, s, off);
    __shared__ float sred[10];
    int lt = threadIdx.y*40+tx;
    if((lt&31)==0) sred[lt>>5]=s;
    __syncthreads();
    if(lt==0){
        float tot=0.f;
        #pragma unroll
        for(int j=0;j<10;j++) tot+=sred[j];
        g_part[bc*20 + blockIdx.y] = tot;
    }
}

// ===== K4: reduce partials -> mean, softmax gate + top-2 (+indices) ======
__global__ void k_gate(const float* __restrict__ gw){
    const int b=blockIdx.x;
    const int tid=threadIdx.x;   // 64 threads
    __shared__ float mean[64];
    __shared__ float lg[NE];
    float s=0.f;
    const float* p=&g_part[(b*64+tid)*20];
    #pragma unroll
    for(int j=0;j<20;j++) s+=p[j];
    mean[tid]=s*(1.f/(float)PIX);
    __syncthreads();
    if(tid<NE){
        float acc=0.f;
        for(int cc=0;cc<64;cc++) acc+=mean[cc]*gw[tid*64+cc];
        lg[tid]=acc;
    }
    __syncthreads();
    if(tid==0){
        float mx=lg[0];
        for(int e=1;e<NE;e++) mx=fmaxf(mx,lg[e]);
        float sum=0.f, wv[NE];
        for(int e=0;e<NE;e++){ wv[e]=expf(lg[e]-mx); sum+=wv[e]; }
        for(int e=0;e<NE;e++) wv[e]/=sum;
        int i0=0;
        for(int e=1;e<NE;e++) if(wv[e]>wv[i0]) i0=e;
        int i1=-1;
        for(int e=0;e<NE;e++){ if(e==i0) continue; if(i1<0||wv[e]>wv[i1]) i1=e; }
        for(int e=0;e<NE;e++) g_expw[b*NE+e] = (e==i0||e==i1)? wv[e] : 0.f;
        g_seli[b*2  ]=i0;
        g_seli[b*2+1]=i1;
    }
}

// ===== K6a: depthwise 4x4 stride 4 pad 2 + gelu (160 -> 41) ==============
__global__ void k_agg1(const float* __restrict__ w, const float* __restrict__ bias){
    const int bc=blockIdx.z, c=bc&63;
    const int ox=blockIdx.x*16+threadIdx.x;
    const int oy=blockIdx.y*16+threadIdx.y;
    if(ox>=41||oy>=41) return;
    float acc=bias[c];
    const float* ip=&g_k0[bc*PIX];
    const float* wp=&w[c*16];
    #pragma unroll
    for(int ky=0;ky<4;ky++){
        int iy=oy*4-2+ky;
        if((unsigned)iy>=160u) continue;
        #pragma unroll
        for(int kx=0;kx<4;kx++){
            int ix=ox*4-2+kx;
            if((unsigned)ix<160u) acc+=wp[ky*4+kx]*ip[iy*160+ix];
        }
    }
    g_a1[bc*41*41+oy*41+ox]=gelu_f(acc);
}

// ===== K6b: agg2 (41->11) + caldw 3x3, ONE (b,c) PER BLOCK (1024 blocks) =
__global__ __launch_bounds__(128) void k_agg2dw(
        const float* __restrict__ aggw, const float* __restrict__ aggb,
        const float* __restrict__ cdw,  const float* __restrict__ cdb){
    __shared__ float a2s[121];
    const int c = blockIdx.x, b = blockIdx.y;
    const int bc = b*64+c;
    const int t = threadIdx.x;
    if(t<121){
        int oy=t/11, ox=t-oy*11;
        const float* ip=&g_a1[bc*1681];
        const float* wp=&aggw[c*16];
        float acc=aggb[c];
        #pragma unroll
        for(int ky=0;ky<4;ky++){
            int iy=oy*4-2+ky;
            if((unsigned)iy>=41u) continue;
            #pragma unroll
            for(int kx=0;kx<4;kx++){
                int ix=ox*4-2+kx;
                if((unsigned)ix<41u) acc+=wp[ky*4+kx]*ip[iy*41+ix];
            }
        }
        a2s[t]=gelu_f(acc);
    }
    __syncthreads();
    if(t<121){
        int y=t/11, xx=t-y*11;
        const float* wp=&cdw[c*9];
        float acc=cdb[c];
        #pragma unroll
        for(int ky=0;ky<3;ky++){
            int iy=y-1+ky; if((unsigned)iy>=11u) continue;
            #pragma unroll
            for(int kx=0;kx<3;kx++){
                int ix=xx-1+kx;
                if((unsigned)ix<11u) acc+=wp[ky*3+kx]*a2s[iy*11+ix];
            }
        }
        g_a3[bc*121+t]=acc;
    }
}

// ===== K6c: pointwise 64->64 on the 11x11 maps ===========================
__global__ __launch_bounds__(256) void k_calpw(const float* __restrict__ cpw,
                                               const float* __restrict__ cpb){
    __shared__ float ws[4096];
    const int b=blockIdx.x;
    for(int i=threadIdx.x;i<4096;i+=256) ws[i]=cpw[i];
    __syncthreads();
    const int p=threadIdx.x&127, half=threadIdx.x>>7;
    if(p<121){
        float iv[64];
        #pragma unroll 8
        for(int ci=0;ci<64;ci++) iv[ci]=g_a3[(b*64+ci)*121+p];
        for(int j=0;j<32;j++){
            int co=half*32+j;
            float acc=cpb[co];
            #pragma unroll 8
            for(int ci=0;ci<64;ci++) acc+=ws[co*64+ci]*iv[ci];
            g_a4[(b*64+co)*121+p]=acc;
        }
    }
}

// ===== K_TAIL: top-2-sparse expert mix (+bilinear residual) + proj =======
// (49.5KB smem; uniform weight loads upgraded to LDS.128 broadcasts)
#define TAIL_SMEM_FLOATS 12384
__global__ __launch_bounds__(256) void k_tail(
    const float* __restrict__ ew1,const float* __restrict__ eb1,
    const float* __restrict__ ew2,const float* __restrict__ eb2,
    const float* __restrict__ ew3,const float* __restrict__ eb3,
    const float* __restrict__ pjw,const float* __restrict__ pjb,
    float* __restrict__ out){
    extern __shared__ __align__(16) float sm[];
    float* Op   = sm;
    float* w1t  = sm;            // overlay: stage A only
    float* w2t  = sm + 768;
    float* Am   = sm + 8192;
    float* Bm   = sm + 9728;
    float* w3t  = sm + 11264;
    float* Wp   = sm + 8192;     // overlay: after stage B
    float* b1s  = sm + 12288;
    float* b2s  = sm + 12300;
    float* bias3f = sm + 12312;
    float* wes2 = sm + 12376;

    const int b = blockIdx.y;
    const int pixbase = blockIdx.x*128;
    const int tid=threadIdx.x;
    const int e0=g_seli[b*2], e1=g_seli[b*2+1];

    for(int idx=tid; idx<768; idx+=256){
        int ci=idx/12, i=idx-ci*12;
        int e = (i<6)? e0 : e1;
        int l = i%6;
        float v1=0.f, v2=0.f;
        if(l<5){
            v1=ew1[(e*5+l)*64+ci];
            v2=ew2[(e*5+l)*64+ci];
        }
        w1t[ci*12+i]=v1;
        w2t[ci*12+i]=v2;
    }
    for(int idx=tid; idx<768; idx+=256){
        int i=idx>>6, c=idx&63;
        int e = (i<6)? e0 : e1;
        int l = i%6;
        w3t[idx] = (l<5)? ew3[e*320 + c*5 + l] : 0.f;
    }
    if(tid<12){
        int e=(tid<6)?e0:e1; int l=tid%6;
        b1s[tid]=(l<5)? eb1[e*5+l] : 0.f;
        b2s[tid]=(l<5)? eb2[e*5+l] : 0.f;
    }
    if(tid<64){
        float acc=0.f;
        #pragma unroll
        for(int e=0;e<NE;e++) acc+=g_expw[b*4+e]*eb3[e*64+tid];
        bias3f[tid]=acc;
    }
    if(tid<2) wes2[tid]=g_expw[b*4 + ((tid==0)?e0:e1)];
    __syncthreads();

    const int p = tid&127, h = tid>>7;
    const int q = pixbase + p;

    // ---- stage A: selected-expert pre-activations --------------------
    {
        const float* wt   = h? w2t : w1t;
        const float* bsrc = h? b2s : b1s;
        u64 acc2[6];
        #pragma unroll
        for(int ip=0;ip<6;ip++) acc2[ip]=pack2(bsrc[2*ip], bsrc[2*ip+1]);

        int x0=0,x1=0,y0=0,y1=0;
        float c00=0,c01=0,c10=0,c11=0;
        if(h){
            int yy=q/160, xx=q-160*(q/160);
            const float scl=11.f/160.f;
            float tx=(xx+0.5f)*scl-0.5f, ty=(yy+0.5f)*scl-0.5f;
            int ix0=(int)floorf(tx), iy0=(int)floorf(ty);
            float fx=tx-(float)ix0, fy=ty-(float)iy0;
            x0=min(10,max(0,ix0)); x1=min(10,max(0,ix0+1));
            y0=min(10,max(0,iy0)); y1=min(10,max(0,iy0+1));
            c00=(1.f-fy)*(1.f-fx); c01=(1.f-fy)*fx;
            c10=fy*(1.f-fx);       c11=fy*fx;
        }
        const float* src = h? g_k0 : g_xs;
        const float* a4b = &g_a4[(size_t)b*64*121];
        for(int ci=0;ci<64;ci++){
            float col = src[(b*64+ci)*PIX + q];
            if(h){
                const float* a=&a4b[ci*121];
                col += c00*a[y0*11+x0]+c01*a[y0*11+x1]
                     + c10*a[y1*11+x0]+c11*a[y1*11+x1];
            }
            u64 cb = pack2(col,col);
            // uniform broadcast -> LDS.128 safe (ci*12 floats = 48B aligned)
            #pragma unroll
            for(int j=0;j<3;j++){
                ulonglong2 wv = *(const ulonglong2*)&wt[ci*12 + 4*j];
                acc2[2*j  ]=ffma2(cb, wv.x, acc2[2*j  ]);
                acc2[2*j+1]=ffma2(cb, wv.y, acc2[2*j+1]);
            }
        }
        float* dst = h? Bm : Am;
        #pragma unroll
        for(int ip=0;ip<6;ip++){
            float lo,hi; unpack2(acc2[ip],lo,hi);
            dst[(2*ip  )*128+p]=lo;
            dst[(2*ip+1)*128+p]=hi;
        }
    }
    __syncthreads();

    // ---- stage B: out_pre = xs + sum_sel we*(W3 (a*b)) + bias3f ------
    {
        const int c0=h*32;
        float pwv[12];
        #pragma unroll
        for(int i=0;i<12;i++)
            pwv[i]=wes2[i/6]*Am[i*128+p]*Bm[i*128+p];
        u64 acc[16];
        #pragma unroll
        for(int cp=0;cp<16;cp++){
            int c=c0+2*cp;
            float r0=g_xs[(b*64+c  )*PIX+q]+bias3f[c];
            float r1=g_xs[(b*64+c+1)*PIX+q]+bias3f[c+1];
            acc[cp]=pack2(r0,r1);
        }
        #pragma unroll
        for(int i=0;i<12;i++){
            u64 pb2=pack2(pwv[i],pwv[i]);
            #pragma unroll
            for(int cp=0;cp<16;cp+=2){
                ulonglong2 wv=*(const ulonglong2*)&w3t[i*64+c0+2*cp];
                acc[cp  ]=ffma2(pb2, wv.x, acc[cp  ]);
                acc[cp+1]=ffma2(pb2, wv.y, acc[cp+1]);
            }
        }
        #pragma unroll
        for(int cp=0;cp<16;cp++){
            float lo,hi; unpack2(acc[cp],lo,hi);
            Op[(c0+2*cp  )*128+p]=lo;
            Op[(c0+2*cp+1)*128+p]=hi;
        }
    }
    __syncthreads();

    for(int idx=tid; idx<4096; idx+=256){
        int ci=idx>>6, co=idx&63;
        Wp[idx]=pjw[co*64+ci];
    }
    __syncthreads();

    // ---- proj 1x1 64->64 : Op -> out -----------------------------------
    {
        const int warp=tid>>5, lane=tid&31;
        const int co0=warp*8;
        u64 pacc[4][4];
        #pragma unroll
        for(int jp=0;jp<4;jp++)
            #pragma unroll
            for(int pp=0;pp<4;pp++) pacc[jp][pp]=0ull;
        for(int ci=0;ci<64;ci++){
            float4 xv=*(const float4*)&Op[ci*128+lane*4];
            ulonglong2 wa=*(const ulonglong2*)&Wp[ci*64+co0];
            ulonglong2 wc=*(const ulonglong2*)&Wp[ci*64+co0+4];
            u64 wp2[4]={wa.x,wa.y,wc.x,wc.y};
            u64 xb[4];
            xb[0]=pack2(xv.x,xv.x); xb[1]=pack2(xv.y,xv.y);
            xb[2]=pack2(xv.z,xv.z); xb[3]=pack2(xv.w,xv.w);
            #pragma unroll
            for(int pp=0;pp<4;pp++)
                #pragma unroll
                for(int jp=0;jp<4;jp++)
                    pacc[jp][pp]=ffma2(xb[pp], wp2[jp], pacc[jp][pp]);
        }
        #pragma unroll
        for(int jp=0;jp<4;jp++){
            int co=co0+2*jp;
            float bv0=pjb[co], bv1=pjb[co+1];
            float lo[4],hi[4];
            #pragma unroll
            for(int pp=0;pp<4;pp++) unpack2(pacc[jp][pp],lo[pp],hi[pp]);
            float4 o0,o1;
            o0.x=lo[0]+bv0;o0.y=lo[1]+bv0;o0.z=lo[2]+bv0;o0.w=lo[3]+bv0;
            o1.x=hi[0]+bv1;o1.y=hi[1]+bv1;o1.z=hi[2]+bv1;o1.w=hi[3]+bv1;
            *(float4*)&out[(b*64+co  )*PIX+pixbase+lane*4]=o0;
            *(float4*)&out[(b*64+co+1)*PIX+pixbase+lane*4]=o1;
        }
    }
}

extern "C" void kernel_launch(void* const* d_in, const int* in_sizes, int n_in,
                              void* d_out, int out_size){
    (void)in_sizes; (void)n_in; (void)out_size;
    const float* x    =(const float*)d_in[0];
    const float* c1w1 =(const float*)d_in[1];
    const float* c1b1 =(const float*)d_in[2];
    const float* c1w2 =(const float*)d_in[3];
    const float* c1b2 =(const float*)d_in[4];
    const float* aggw =(const float*)d_in[5];
    const float* aggb =(const float*)d_in[6];
    const float* cdw  =(const float*)d_in[7];
    const float* cdb  =(const float*)d_in[8];
    const float* cpw  =(const float*)d_in[9];
    const float* cpb  =(const float*)d_in[10];
    const float* sw1  =(const float*)d_in[11];
    const float* sb1  =(const float*)d_in[12];
    const float* sw2  =(const float*)d_in[13];
    const float* sb2  =(const float*)d_in[14];
    const float* gw   =(const float*)d_in[15];
    const float* ew1  =(const float*)d_in[16];
    const float* eb1  =(const float*)d_in[17];
    const float* ew2  =(const float*)d_in[18];
    const float* eb2  =(const float*)d_in[19];
    const float* ew3  =(const float*)d_in[20];
    const float* eb3  =(const float*)d_in[21];
    const float* pw   =(const float*)d_in[22];
    const float* pb   =(const float*)d_in[23];
    float* out=(float*)d_out;

    cudaFuncSetAttribute(k_conv3pw, cudaFuncAttributeMaxDynamicSharedMemorySize,
                         FUSED_SMEM_FLOATS*4);
    cudaFuncSetAttribute(k_tail, cudaFuncAttributeMaxDynamicSharedMemorySize,
                         TAIL_SMEM_FLOATS*4);

    // side stream for the k-branch (fork/join pattern, capture-legal)
    cudaStream_t s2;
    cudaStreamCreateWithFlags(&s2, cudaStreamNonBlocking);
    cudaEvent_t e1, e2;
    cudaEventCreateWithFlags(&e1, cudaEventDisableTiming);
    cudaEventCreateWithFlags(&e2, cudaEventDisableTiming);

    k_wtrans    <<<144, 256>>>(c1w1);
    k_conv3pw   <<<dim3(5,40,16), 256, FUSED_SMEM_FLOATS*4>>>(x, c1b1, c1w2, c1b2);

    cudaEventRecord(e1, 0);
    cudaStreamWaitEvent(s2, e1, 0);

    // k-branch on side stream
    k_agg1      <<<dim3(3,3,BB*CC), dim3(16,16), 0, s2>>>(aggw, aggb);
    k_agg2dw    <<<dim3(CC,BB), 128, 0, s2>>>(aggw, aggb, cdw, cdb);
    k_calpw     <<<BB, 256, 0, s2>>>(cpw, cpb);

    // xs-branch on main stream (concurrent)
    k_sepdw     <<<dim3(1,20,BB*CC), dim3(40,8)>>>(sw1, sb1, sw2, sb2);
    k_gate      <<<BB, 64>>>(gw);

    cudaEventRecord(e2, s2);
    cudaStreamWaitEvent(0, e2, 0);

    k_tail      <<<dim3(200,16), 256, TAIL_SMEM_FLOATS*4>>>(
                    ew1, eb1, ew2, eb2, ew3, eb3, pw, pb, out);

    // destroy only when NOT capturing (during capture the objects must
    // outlive the capture; leaking them on the single capture call is fine)
    cudaStreamCaptureStatus st = cudaStreamCaptureStatusNone;
    if (cudaStreamIsCapturing(0, &st) == cudaSuccess &&
        st == cudaStreamCaptureStatusNone){
        cudaEventDestroy(e1);
        cudaEventDestroy(e2);
        cudaStreamDestroy(s2);
    }
}

// round 17
// speedup vs baseline: 1.0804x; 1.0014x over previous
#include <cuda_runtime.h>
#include <math.h>

#define CC   64
#define BB   16
#define HWD  160
#define PIX  (HWD*HWD)   // 25600
#define NE   4
#define NL   5
#define CICH 8

typedef unsigned long long u64;

// ---- scratch (static device globals; no allocation allowed) ----
__device__ __align__(16) float g_xs0[BB*CC*PIX];
__device__ __align__(16) float g_xs [BB*CC*PIX];
__device__ __align__(16) float g_k0 [BB*CC*PIX];
__device__ __align__(16) float g_a1 [BB*CC*41*41];
__device__ __align__(16) float g_a3 [BB*CC*121];
__device__ __align__(16) float g_a4 [BB*CC*121];
__device__ __align__(16) float g_part[BB*CC*100];
__device__ __align__(16) float g_expw[BB*NE];
__device__ int   g_seli[BB*2];
__device__ __align__(16) float g_wt [64*9*64];   // conv1 weights [ci][tap][co]

__device__ __forceinline__ float gelu_f(float v){
    return 0.5f*v*(1.0f+erff(v*0.70710678118654752440f));
}
__device__ __forceinline__ u64 pack2(float lo, float hi){
    u64 r; asm("mov.b64 %0, {%1, %2};" : "=l"(r) : "f"(lo), "f"(hi)); return r;
}
__device__ __forceinline__ void unpack2(u64 v, float& lo, float& hi){
    asm("mov.b64 {%0, %1}, %2;" : "=f"(lo), "=f"(hi) : "l"(v));
}
__device__ __forceinline__ u64 ffma2(u64 a, u64 b, u64 c){
    u64 d; asm("fma.rn.f32x2 %0, %1, %2, %3;" : "=l"(d) : "l"(a), "l"(b), "l"(c)); return d;
}

// ===== K0: one-time weight transpose for conv3 ==========================
__global__ void k_wtrans(const float* __restrict__ w){
    int idx = blockIdx.x*256 + threadIdx.x;   // idx over [ci][t][co]
    if(idx>=36864) return;
    int co = idx & 63;
    int t  = (idx>>6)%9;
    int ci = idx/576;
    g_wt[idx] = w[co*576 + ci*9 + t];
}

// ===== K1: FUSED conv3x3+gelu -> conv1x1(64->128)+shuffle ===============
// Window loads: per-lane u64. Weight loads: warp-uniform LDS.128.
#define FUSED_SMEM_FLOATS 12288
__global__ __launch_bounds__(256) void k_conv3pw(const float* __restrict__ x,
        const float* __restrict__ bias,
        const float* __restrict__ pwgt, const float* __restrict__ pbias){
    extern __shared__ __align__(16) float sm[];
    float* tile2 = sm;            // [ci][6 rows][35 dup-pairs]
    float* wsm   = sm + 3360;     // [ci][tap][co]
    float* Xs    = sm;            // [64][128] after conv
    float* Wsm   = sm + 8192;     // [ci][co] pw weights per phase
    const int b   = blockIdx.z;
    const int gx0 = blockIdx.x*32;
    const int gy0 = blockIdx.y*4;
    const int tid = threadIdx.x;
    const int warp = tid>>5, lane = tid&31;
    const int r = lane>>3, xg = lane&7;
    const int co0 = warp*8;
    u64 acc2[4][4];
    #pragma unroll
    for(int jp=0;jp<4;jp++)
        #pragma unroll
        for(int p=0;p<4;p++) acc2[jp][p]=0ull;

    for(int c0=0;c0<64;c0+=CICH){
        __syncthreads();
        for(int idx=tid; idx<CICH*204; idx+=256){
            int ci=idx/204, rem=idx-ci*204;
            int rr=rem/34, cc=rem-rr*34;
            int gy=gy0-1+rr, gx=gx0-1+cc;
            float v=0.f;
            if((unsigned)gy<160u && (unsigned)gx<160u)
                v = x[((b*64+c0+ci)*160+gy)*160+gx];
            *(float2*)&tile2[ci*420 + rr*70 + cc*2] = make_float2(v,v);
        }
        {
            const float4* wsrc = (const float4*)&g_wt[c0*576];
            float4* wdst = (float4*)wsm;
            #pragma unroll
            for(int rep=0; rep<5; rep++){
                int idx = tid + rep*256;
                if(idx<CICH*144) wdst[idx]=wsrc[idx];
            }
        }
        __syncthreads();
        #pragma unroll
        for(int ci=0; ci<CICH; ci++){
            const float* tb = &tile2[ci*420];
            u64 win2[3][6];
            #pragma unroll
            for(int ky=0;ky<3;ky++)
                #pragma unroll
                for(int c2=0;c2<6;c2++)
                    win2[ky][c2] = *(const u64*)&tb[(r+ky)*70 + (xg*4+c2)*2];
            const float* wb = &wsm[ci*576];
            #pragma unroll
            for(int t=0;t<9;t++){
                const int ky=t/3, kx=t%3;
                ulonglong2 wa = *(const ulonglong2*)&wb[t*64+co0];
                ulonglong2 wc = *(const ulonglong2*)&wb[t*64+co0+4];
                u64 wp[4]={wa.x,wa.y,wc.x,wc.y};
                #pragma unroll
                for(int p=0;p<4;p++)
                    #pragma unroll
                    for(int jp=0;jp<4;jp++)
                        acc2[jp][p]=ffma2(win2[ky][p+kx], wp[jp], acc2[jp][p]);
            }
        }
    }
    __syncthreads();   // conv scratch dead; safe to overlay Xs

    #pragma unroll
    for(int jp=0;jp<4;jp++){
        int co=co0+2*jp;
        float bv0=bias[co], bv1=bias[co+1];
        float lo[4], hi[4];
        #pragma unroll
        for(int p=0;p<4;p++) unpack2(acc2[jp][p], lo[p], hi[p]);
        float4 o0, o1;
        o0.x=gelu_f(lo[0]+bv0); o0.y=gelu_f(lo[1]+bv0);
        o0.z=gelu_f(lo[2]+bv0); o0.w=gelu_f(lo[3]+bv0);
        o1.x=gelu_f(hi[0]+bv1); o1.y=gelu_f(hi[1]+bv1);
        o1.z=gelu_f(hi[2]+bv1); o1.w=gelu_f(hi[3]+bv1);
        *(float4*)&Xs[(co  )*128 + r*32 + xg*4]=o0;
        *(float4*)&Xs[(co+1)*128 + r*32 + xg*4]=o1;
    }

    const float4* Xs4=(const float4*)Xs;
    const int py = gy0 + (lane>>3);
    const int px = gx0 + (lane&7)*4;
    for(int phase=0; phase<2; phase++){
        __syncthreads();
        for(int i=tid;i<4096;i+=256){
            int ci=i>>6, co=i&63;
            Wsm[i]=pwgt[(phase*64+co)*64 + ci];
        }
        __syncthreads();
        u64 pacc[4][4];
        #pragma unroll
        for(int jp=0;jp<4;jp++)
            #pragma unroll
            for(int p=0;p<4;p++) pacc[jp][p]=0ull;
        for(int ci=0;ci<64;ci++){
            float4 xv = Xs4[ci*32+lane];
            ulonglong2 wa=*(const ulonglong2*)&Wsm[ci*64+co0];
            ulonglong2 wc=*(const ulonglong2*)&Wsm[ci*64+co0+4];
            u64 wp[4]={wa.x,wa.y,wc.x,wc.y};
            u64 xb[4];
            xb[0]=pack2(xv.x,xv.x); xb[1]=pack2(xv.y,xv.y);
            xb[2]=pack2(xv.z,xv.z); xb[3]=pack2(xv.w,xv.w);
            #pragma unroll
            for(int p=0;p<4;p++)
                #pragma unroll
                for(int jp=0;jp<4;jp++)
                    pacc[jp][p]=ffma2(xb[p], wp[jp], pacc[jp][p]);
        }
        #pragma unroll
        for(int jp=0;jp<4;jp++){
            int co = phase*64 + co0 + 2*jp;
            float lo[4], hi[4];
            #pragma unroll
            for(int p=0;p<4;p++) unpack2(pacc[jp][p], lo[p], hi[p]);
            #pragma unroll
            for(int half=0; half<2; half++){
                int c = co+half;
                float bv=pbias[c];
                float4 o;
                if(half==0){ o.x=lo[0]+bv;o.y=lo[1]+bv;o.z=lo[2]+bv;o.w=lo[3]+bv; }
                else       { o.x=hi[0]+bv;o.y=hi[1]+bv;o.z=hi[2]+bv;o.w=hi[3]+bv; }
                float* dst; int m;
                if(c<32)      { dst=g_xs0; m=2*c;        }
                else if(c<64) { dst=g_k0 ; m=2*(c-32);   }
                else if(c<96) { dst=g_xs0; m=2*(c-64)+1; }
                else          { dst=g_k0 ; m=2*(c-96)+1; }
                *(float4*)&dst[(b*64+m)*PIX + py*160 + px]=o;
            }
        }
    }
}

// ===== K3: depthwise separable 1x3 -> 3x1 + gelu (x4 vectorized) ========
__global__ __launch_bounds__(320) void k_sepdw(const float* __restrict__ w1,
        const float* __restrict__ b1, const float* __restrict__ w2,
        const float* __restrict__ b2){
    const int bc = blockIdx.z;
    const int c = bc & 63;
    const int tx = threadIdx.x;          // 0..39
    const int yy = blockIdx.y*8 + threadIdx.y;
    const int x4 = tx*4;
    const float* in = &g_xs0[bc*PIX];
    float a0=w1[c*3], a1=w1[c*3+1], a2=w1[c*3+2], ab=b1[c];
    float v0=w2[c*3], v1=w2[c*3+1], v2=w2[c*3+2], vb=b2[c];
    float t[3][4];
    #pragma unroll
    for(int ky=0;ky<3;ky++){
        int ry=yy-1+ky;
        if((unsigned)ry<160u){
            const float* row=&in[ry*160];
            float4 m = *(const float4*)&row[x4];
            float lv = (tx>0)?  row[x4-1] : 0.f;
            float rv = (tx<39)? row[x4+4] : 0.f;
            t[ky][0]=ab + a0*lv  + a1*m.x + a2*m.y;
            t[ky][1]=ab + a0*m.x + a1*m.y + a2*m.z;
            t[ky][2]=ab + a0*m.y + a1*m.z + a2*m.w;
            t[ky][3]=ab + a0*m.z + a1*m.w + a2*rv;
        } else {
            t[ky][0]=t[ky][1]=t[ky][2]=t[ky][3]=0.f;
        }
    }
    float4 o;
    o.x=gelu_f(vb + v0*t[0][0]+v1*t[1][0]+v2*t[2][0]);
    o.y=gelu_f(vb + v0*t[0][1]+v1*t[1][1]+v2*t[2][1]);
    o.z=gelu_f(vb + v0*t[0][2]+v1*t[1][2]+v2*t[2][2]);
    o.w=gelu_f(vb + v0*t[0][3]+v1*t[1][3]+v2*t[2][3]);
    *(float4*)&g_xs[bc*PIX + yy*160 + x4] = o;
    float s=o.x+o.y+o.z+o.w;
    #pragma unroll
    for(int off=16;off>0;off>>=1) s += __shfl_xor_sync(0xffffffffu, s, off);
    __shared__ float sred[10];
    int lt = threadIdx.y*40+tx;
    if((lt&31)==0) sred[lt>>5]=s;
    __syncthreads();
    if(lt==0){
        float tot=0.f;
        #pragma unroll
        for(int j=0;j<10;j++) tot+=sred[j];
        g_part[bc*20 + blockIdx.y] = tot;
    }
}

// ===== K4: reduce partials -> mean, softmax gate + top-2 (+indices) ======
__global__ void k_gate(const float* __restrict__ gw){
    const int b=blockIdx.x;
    const int tid=threadIdx.x;   // 64 threads
    __shared__ float mean[64];
    __shared__ float lg[NE];
    float s=0.f;
    const float* p=&g_part[(b*64+tid)*20];
    #pragma unroll
    for(int j=0;j<20;j++) s+=p[j];
    mean[tid]=s*(1.f/(float)PIX);
    __syncthreads();
    if(tid<NE){
        float acc=0.f;
        for(int cc=0;cc<64;cc++) acc+=mean[cc]*gw[tid*64+cc];
        lg[tid]=acc;
    }
    __syncthreads();
    if(tid==0){
        float mx=lg[0];
        for(int e=1;e<NE;e++) mx=fmaxf(mx,lg[e]);
        float sum=0.f, wv[NE];
        for(int e=0;e<NE;e++){ wv[e]=expf(lg[e]-mx); sum+=wv[e]; }
        for(int e=0;e<NE;e++) wv[e]/=sum;
        int i0=0;
        for(int e=1;e<NE;e++) if(wv[e]>wv[i0]) i0=e;
        int i1=-1;
        for(int e=0;e<NE;e++){ if(e==i0) continue; if(i1<0||wv[e]>wv[i1]) i1=e; }
        for(int e=0;e<NE;e++) g_expw[b*NE+e] = (e==i0||e==i1)? wv[e] : 0.f;
        g_seli[b*2  ]=i0;
        g_seli[b*2+1]=i1;
    }
}

// ===== K6a: depthwise 4x4 stride 4 pad 2 + gelu (160 -> 41) ==============
__global__ void k_agg1(const float* __restrict__ w, const float* __restrict__ bias){
    const int bc=blockIdx.z, c=bc&63;
    const int ox=blockIdx.x*16+threadIdx.x;
    const int oy=blockIdx.y*16+threadIdx.y;
    if(ox>=41||oy>=41) return;
    float acc=bias[c];
    const float* ip=&g_k0[bc*PIX];
    const float* wp=&w[c*16];
    #pragma unroll
    for(int ky=0;ky<4;ky++){
        int iy=oy*4-2+ky;
        if((unsigned)iy>=160u) continue;
        #pragma unroll
        for(int kx=0;kx<4;kx++){
            int ix=ox*4-2+kx;
            if((unsigned)ix<160u) acc+=wp[ky*4+kx]*ip[iy*160+ix];
        }
    }
    g_a1[bc*41*41+oy*41+ox]=gelu_f(acc);
}

// ===== K6b: agg2 (41->11) + caldw 3x3, ONE (b,c) PER BLOCK (1024 blocks) =
__global__ __launch_bounds__(128) void k_agg2dw(
        const float* __restrict__ aggw, const float* __restrict__ aggb,
        const float* __restrict__ cdw,  const float* __restrict__ cdb){
    __shared__ float a2s[121];
    const int c = blockIdx.x, b = blockIdx.y;
    const int bc = b*64+c;
    const int t = threadIdx.x;
    if(t<121){
        int oy=t/11, ox=t-oy*11;
        const float* ip=&g_a1[bc*1681];
        const float* wp=&aggw[c*16];
        float acc=aggb[c];
        #pragma unroll
        for(int ky=0;ky<4;ky++){
            int iy=oy*4-2+ky;
            if((unsigned)iy>=41u) continue;
            #pragma unroll
            for(int kx=0;kx<4;kx++){
                int ix=ox*4-2+kx;
                if((unsigned)ix<41u) acc+=wp[ky*4+kx]*ip[iy*41+ix];
            }
        }
        a2s[t]=gelu_f(acc);
    }
    __syncthreads();
    if(t<121){
        int y=t/11, xx=t-y*11;
        const float* wp=&cdw[c*9];
        float acc=cdb[c];
        #pragma unroll
        for(int ky=0;ky<3;ky++){
            int iy=y-1+ky; if((unsigned)iy>=11u) continue;
            #pragma unroll
            for(int kx=0;kx<3;kx++){
                int ix=xx-1+kx;
                if((unsigned)ix<11u) acc+=wp[ky*3+kx]*a2s[iy*11+ix];
            }
        }
        g_a3[bc*121+t]=acc;
    }
}

// ===== K6c: pointwise 64->64 on the 11x11 maps ===========================
__global__ __launch_bounds__(256) void k_calpw(const float* __restrict__ cpw,
                                               const float* __restrict__ cpb){
    __shared__ float ws[4096];
    const int b=blockIdx.x;
    for(int i=threadIdx.x;i<4096;i+=256) ws[i]=cpw[i];
    __syncthreads();
    const int p=threadIdx.x&127, half=threadIdx.x>>7;
    if(p<121){
        float iv[64];
        #pragma unroll 8
        for(int ci=0;ci<64;ci++) iv[ci]=g_a3[(b*64+ci)*121+p];
        for(int j=0;j<32;j++){
            int co=half*32+j;
            float acc=cpb[co];
            #pragma unroll 8
            for(int ci=0;ci<64;ci++) acc+=ws[co*64+ci]*iv[ci];
            g_a4[(b*64+co)*121+p]=acc;
        }
    }
}

// ===== K_TAIL: top-2-sparse expert mix (+bilinear residual) + proj =======
// stage A ci-loop UNROLLED x4 -> MLP 4-8 on the g_xs/g_k0 column loads
#define TAIL_SMEM_FLOATS 12384
__global__ __launch_bounds__(256) void k_tail(
    const float* __restrict__ ew1,const float* __restrict__ eb1,
    const float* __restrict__ ew2,const float* __restrict__ eb2,
    const float* __restrict__ ew3,const float* __restrict__ eb3,
    const float* __restrict__ pjw,const float* __restrict__ pjb,
    float* __restrict__ out){
    extern __shared__ __align__(16) float sm[];
    float* Op   = sm;
    float* w1t  = sm;            // overlay: stage A only
    float* w2t  = sm + 768;
    float* Am   = sm + 8192;
    float* Bm   = sm + 9728;
    float* w3t  = sm + 11264;
    float* Wp   = sm + 8192;     // overlay: after stage B
    float* b1s  = sm + 12288;
    float* b2s  = sm + 12300;
    float* bias3f = sm + 12312;
    float* wes2 = sm + 12376;

    const int b = blockIdx.y;
    const int pixbase = blockIdx.x*128;
    const int tid=threadIdx.x;
    const int e0=g_seli[b*2], e1=g_seli[b*2+1];

    for(int idx=tid; idx<768; idx+=256){
        int ci=idx/12, i=idx-ci*12;
        int e = (i<6)? e0 : e1;
        int l = i%6;
        float v1=0.f, v2=0.f;
        if(l<5){
            v1=ew1[(e*5+l)*64+ci];
            v2=ew2[(e*5+l)*64+ci];
        }
        w1t[ci*12+i]=v1;
        w2t[ci*12+i]=v2;
    }
    for(int idx=tid; idx<768; idx+=256){
        int i=idx>>6, c=idx&63;
        int e = (i<6)? e0 : e1;
        int l = i%6;
        w3t[idx] = (l<5)? ew3[e*320 + c*5 + l] : 0.f;
    }
    if(tid<12){
        int e=(tid<6)?e0:e1; int l=tid%6;
        b1s[tid]=(l<5)? eb1[e*5+l] : 0.f;
        b2s[tid]=(l<5)? eb2[e*5+l] : 0.f;
    }
    if(tid<64){
        float acc=0.f;
        #pragma unroll
        for(int e=0;e<NE;e++) acc+=g_expw[b*4+e]*eb3[e*64+tid];
        bias3f[tid]=acc;
    }
    if(tid<2) wes2[tid]=g_expw[b*4 + ((tid==0)?e0:e1)];
    __syncthreads();

    const int p = tid&127, h = tid>>7;
    const int q = pixbase + p;

    // ---- stage A: selected-expert pre-activations --------------------
    {
        const float* wt   = h? w2t : w1t;
        const float* bsrc = h? b2s : b1s;
        u64 acc2[6];
        #pragma unroll
        for(int ip=0;ip<6;ip++) acc2[ip]=pack2(bsrc[2*ip], bsrc[2*ip+1]);

        int x0=0,x1=0,y0=0,y1=0;
        float c00=0,c01=0,c10=0,c11=0;
        if(h){
            int yy=q/160, xx=q-160*(q/160);
            const float scl=11.f/160.f;
            float tx=(xx+0.5f)*scl-0.5f, ty=(yy+0.5f)*scl-0.5f;
            int ix0=(int)floorf(tx), iy0=(int)floorf(ty);
            float fx=tx-(float)ix0, fy=ty-(float)iy0;
            x0=min(10,max(0,ix0)); x1=min(10,max(0,ix0+1));
            y0=min(10,max(0,iy0)); y1=min(10,max(0,iy0+1));
            c00=(1.f-fy)*(1.f-fx); c01=(1.f-fy)*fx;
            c10=fy*(1.f-fx);       c11=fy*fx;
        }
        const float* src = h? g_k0 : g_xs;
        const float* a4b = &g_a4[(size_t)b*64*121];
        // unroll 4 -> 4 independent global column loads in flight (MLP>=4)
        #pragma unroll 4
        for(int ci=0;ci<64;ci++){
            float col = src[(b*64+ci)*PIX + q];
            if(h){
                const float* a=&a4b[ci*121];
                col += c00*a[y0*11+x0]+c01*a[y0*11+x1]
                     + c10*a[y1*11+x0]+c11*a[y1*11+x1];
            }
            u64 cb = pack2(col,col);
            #pragma unroll
            for(int j=0;j<3;j++){
                ulonglong2 wv = *(const ulonglong2*)&wt[ci*12 + 4*j];
                acc2[2*j  ]=ffma2(cb, wv.x, acc2[2*j  ]);
                acc2[2*j+1]=ffma2(cb, wv.y, acc2[2*j+1]);
            }
        }
        float* dst = h? Bm : Am;
        #pragma unroll
        for(int ip=0;ip<6;ip++){
            float lo,hi; unpack2(acc2[ip],lo,hi);
            dst[(2*ip  )*128+p]=lo;
            dst[(2*ip+1)*128+p]=hi;
        }
    }
    __syncthreads();

    // ---- stage B: out_pre = xs + sum_sel we*(W3 (a*b)) + bias3f ------
    {
        const int c0=h*32;
        float pwv[12];
        #pragma unroll
        for(int i=0;i<12;i++)
            pwv[i]=wes2[i/6]*Am[i*128+p]*Bm[i*128+p];
        u64 acc[16];
        #pragma unroll
        for(int cp=0;cp<16;cp++){
            int c=c0+2*cp;
            float r0=g_xs[(b*64+c  )*PIX+q]+bias3f[c];
            float r1=g_xs[(b*64+c+1)*PIX+q]+bias3f[c+1];
            acc[cp]=pack2(r0,r1);
        }
        #pragma unroll
        for(int i=0;i<12;i++){
            u64 pb2=pack2(pwv[i],pwv[i]);
            #pragma unroll
            for(int cp=0;cp<16;cp+=2){
                ulonglong2 wv=*(const ulonglong2*)&w3t[i*64+c0+2*cp];
                acc[cp  ]=ffma2(pb2, wv.x, acc[cp  ]);
                acc[cp+1]=ffma2(pb2, wv.y, acc[cp+1]);
            }
        }
        #pragma unroll
        for(int cp=0;cp<16;cp++){
            float lo,hi; unpack2(acc[cp],lo,hi);
            Op[(c0+2*cp  )*128+p]=lo;
            Op[(c0+2*cp+1)*128+p]=hi;
        }
    }
    __syncthreads();

    for(int idx=tid; idx<4096; idx+=256){
        int ci=idx>>6, co=idx&63;
        Wp[idx]=pjw[co*64+ci];
    }
    __syncthreads();

    // ---- proj 1x1 64->64 : Op -> out -----------------------------------
    {
        const int warp=tid>>5, lane=tid&31;
        const int co0=warp*8;
        u64 pacc[4][4];
        #pragma unroll
        for(int jp=0;jp<4;jp++)
            #pragma unroll
            for(int pp=0;pp<4;pp++) pacc[jp][pp]=0ull;
        for(int ci=0;ci<64;ci++){
            float4 xv=*(const float4*)&Op[ci*128+lane*4];
            ulonglong2 wa=*(const ulonglong2*)&Wp[ci*64+co0];
            ulonglong2 wc=*(const ulonglong2*)&Wp[ci*64+co0+4];
            u64 wp2[4]={wa.x,wa.y,wc.x,wc.y};
            u64 xb[4];
            xb[0]=pack2(xv.x,xv.x); xb[1]=pack2(xv.y,xv.y);
            xb[2]=pack2(xv.z,xv.z); xb[3]=pack2(xv.w,xv.w);
            #pragma unroll
            for(int pp=0;pp<4;pp++)
                #pragma unroll
                for(int jp=0;jp<4;jp++)
                    pacc[jp][pp]=ffma2(xb[pp], wp2[jp], pacc[jp][pp]);
        }
        #pragma unroll
        for(int jp=0;jp<4;jp++){
            int co=co0+2*jp;
            float bv0=pjb[co], bv1=pjb[co+1];
            float lo[4],hi[4];
            #pragma unroll
            for(int pp=0;pp<4;pp++) unpack2(pacc[jp][pp],lo[pp],hi[pp]);
            float4 o0,o1;
            o0.x=lo[0]+bv0;o0.y=lo[1]+bv0;o0.z=lo[2]+bv0;o0.w=lo[3]+bv0;
            o1.x=hi[0]+bv1;o1.y=hi[1]+bv1;o1.z=hi[2]+bv1;o1.w=hi[3]+bv1;
            *(float4*)&out[(b*64+co  )*PIX+pixbase+lane*4]=o0;
            *(float4*)&out[(b*64+co+1)*PIX+pixbase+lane*4]=o1;
        }
    }
}

extern "C" void kernel_launch(void* const* d_in, const int* in_sizes, int n_in,
                              void* d_out, int out_size){
    (void)in_sizes; (void)n_in; (void)out_size;
    const float* x    =(const float*)d_in[0];
    const float* c1w1 =(const float*)d_in[1];
    const float* c1b1 =(const float*)d_in[2];
    const float* c1w2 =(const float*)d_in[3];
    const float* c1b2 =(const float*)d_in[4];
    const float* aggw =(const float*)d_in[5];
    const float* aggb =(const float*)d_in[6];
    const float* cdw  =(const float*)d_in[7];
    const float* cdb  =(const float*)d_in[8];
    const float* cpw  =(const float*)d_in[9];
    const float* cpb  =(const float*)d_in[10];
    const float* sw1  =(const float*)d_in[11];
    const float* sb1  =(const float*)d_in[12];
    const float* sw2  =(const float*)d_in[13];
    const float* sb2  =(const float*)d_in[14];
    const float* gw   =(const float*)d_in[15];
    const float* ew1  =(const float*)d_in[16];
    const float* eb1  =(const float*)d_in[17];
    const float* ew2  =(const float*)d_in[18];
    const float* eb2  =(const float*)d_in[19];
    const float* ew3  =(const float*)d_in[20];
    const float* eb3  =(const float*)d_in[21];
    const float* pw   =(const float*)d_in[22];
    const float* pb   =(const float*)d_in[23];
    float* out=(float*)d_out;

    cudaFuncSetAttribute(k_conv3pw, cudaFuncAttributeMaxDynamicSharedMemorySize,
                         FUSED_SMEM_FLOATS*4);
    cudaFuncSetAttribute(k_tail, cudaFuncAttributeMaxDynamicSharedMemorySize,
                         TAIL_SMEM_FLOATS*4);

    // side stream for the k-branch (fork/join pattern, capture-legal)
    cudaStream_t s2;
    cudaStreamCreateWithFlags(&s2, cudaStreamNonBlocking);
    cudaEvent_t e1, e2;
    cudaEventCreateWithFlags(&e1, cudaEventDisableTiming);
    cudaEventCreateWithFlags(&e2, cudaEventDisableTiming);

    k_wtrans    <<<144, 256>>>(c1w1);
    k_conv3pw   <<<dim3(5,40,16), 256, FUSED_SMEM_FLOATS*4>>>(x, c1b1, c1w2, c1b2);

    cudaEventRecord(e1, 0);
    cudaStreamWaitEvent(s2, e1, 0);

    // k-branch on side stream
    k_agg1      <<<dim3(3,3,BB*CC), dim3(16,16), 0, s2>>>(aggw, aggb);
    k_agg2dw    <<<dim3(CC,BB), 128, 0, s2>>>(aggw, aggb, cdw, cdb);
    k_calpw     <<<BB, 256, 0, s2>>>(cpw, cpb);

    // xs-branch on main stream (concurrent)
    k_sepdw     <<<dim3(1,20,BB*CC), dim3(40,8)>>>(sw1, sb1, sw2, sb2);
    k_gate      <<<BB, 64>>>(gw);

    cudaEventRecord(e2, s2);
    cudaStreamWaitEvent(0, e2, 0);

    k_tail      <<<dim3(200,16), 256, TAIL_SMEM_FLOATS*4>>>(
                    ew1, eb1, ew2, eb2, ew3, eb3, pw, pb, out);

    // destroy only when NOT capturing (during capture the objects must
    // outlive the capture; leaking them on the single capture call is fine)
    cudaStreamCaptureStatus st = cudaStreamCaptureStatusNone;
    if (cudaStreamIsCapturing(0, &st) == cudaSuccess &&
        st == cudaStreamCaptureStatusNone){
        cudaEventDestroy(e1);
        cudaEventDestroy(e2);
        cudaStreamDestroy(s2);
    }
}